// round 8
// baseline (speedup 1.0000x reference)
#include <cuda_runtime.h>
#include <math.h>

#define BB 2
#define SS 1024
#define DM 1024
#define NH 16
#define DH 64
#define MROWS (BB*SS)
#define MAXN 0.996f

__device__ float g_qkv[3][MROWS*DM];
__device__ float g_aux[3][MROWS*NH];        // per-(row,head) final ||y||^2
__device__ unsigned g_kfrag[32*16*8*512];   // K  mma-frag order
__device__ unsigned g_vfrag[32*16*8*512];   // gamma*V mma-frag order
__device__ float4   g_sck[32*1024];         // per (bh,key): {k2, 1/(1-k2), gm1, e^mask}
__device__ unsigned g_xt[MROWS*DM];         // tf32(X)
__device__ unsigned g_zt[3][DM*DM];         // tf32(Z)
__device__ float    g_rowsq[MROWS];         // ||x_row||^2
__device__ float4   g_cols[3][DM];          // {2cosh(2r)/zn, 2zn, sinh(2r), 0}

__device__ __forceinline__ unsigned f2tf32(float x) {
    unsigned r; asm("cvt.rna.tf32.f32 %0, %1;" : "=r"(r) : "f"(x)); return r;
}
__device__ __forceinline__ void mma8(float* d, const unsigned* a, const unsigned* b) {
    asm volatile("mma.sync.aligned.m16n8k8.row.col.f32.tf32.tf32.f32 "
        "{%0,%1,%2,%3}, {%4,%5,%6,%7}, {%8,%9}, {%0,%1,%2,%3};"
        : "+f"(d[0]), "+f"(d[1]), "+f"(d[2]), "+f"(d[3])
        : "r"(a[0]), "r"(a[1]), "r"(a[2]), "r"(a[3]), "r"(b[0]), "r"(b[1]));
}
__device__ __forceinline__ float fsqrt_a(float x){float r;asm("sqrt.approx.f32 %0,%1;":"=f"(r):"f"(x));return r;}
__device__ __forceinline__ float frcp_a (float x){float r;asm("rcp.approx.f32 %0,%1;" :"=f"(r):"f"(x));return r;}
__device__ __forceinline__ float flg2_a (float x){float r;asm("lg2.approx.f32 %0,%1;" :"=f"(r):"f"(x));return r;}
__device__ __forceinline__ float fex2_a (float x){float r;asm("ex2.approx.f32 %0,%1;" :"=f"(r):"f"(x));return r;}
__device__ __forceinline__ void cp16(unsigned s, const void* g) {
    asm volatile("cp.async.ca.shared.global [%0], [%1], 16;" :: "r"(s), "l"(g));
}

// ---------------------------------------------------------------------------
// Kernel 0: convert X,Z to tf32; compute row norms + per-column epilogue scalars
// blocks 0..255: X (8 rows each, warp/row). blocks 256..303: Z (64 cols each).
// ---------------------------------------------------------------------------
__global__ __launch_bounds__(256)
void cvt_norm_kernel(const float* __restrict__ X,
                     const float* __restrict__ qz, const float* __restrict__ kz,
                     const float* __restrict__ vz, const float* __restrict__ qr,
                     const float* __restrict__ kr, const float* __restrict__ vr) {
    int bx = blockIdx.x, t = threadIdx.x;
    if (bx < 256) {
        int row = bx * 8 + (t >> 5), lane = t & 31;
        const float* xr = X + row * DM;
        unsigned* xo = g_xt + row * DM;
        float s = 0.f;
        #pragma unroll
        for (int i = 0; i < 8; i++) {
            float4 v = *(const float4*)&xr[(i * 32 + lane) * 4];
            s = fmaf(v.x, v.x, fmaf(v.y, v.y, fmaf(v.z, v.z, fmaf(v.w, v.w, s))));
            *(uint4*)&xo[(i * 32 + lane) * 4] =
                make_uint4(f2tf32(v.x), f2tf32(v.y), f2tf32(v.z), f2tf32(v.w));
        }
        #pragma unroll
        for (int off = 16; off > 0; off >>= 1) s += __shfl_xor_sync(0xffffffffu, s, off);
        if (lane == 0) g_rowsq[row] = s;
    } else {
        int which = (bx - 256) >> 4;
        int c0 = ((bx - 256) & 15) * 64;
        const float* Z = (which == 0) ? qz : (which == 1) ? kz : vz;
        const float* R = (which == 0) ? qr : (which == 1) ? kr : vr;
        int tx = t & 63, ty = t >> 6;
        int col = c0 + tx;
        float s = 0.f;
        #pragma unroll 8
        for (int rr = ty; rr < DM; rr += 4) {
            float v = Z[rr * DM + col];
            s = fmaf(v, v, s);
            g_zt[which][rr * DM + col] = f2tf32(v);
        }
        __shared__ float red[256];
        red[t] = s;
        __syncthreads();
        if (ty == 0) {
            float zs = red[tx] + red[tx + 64] + red[tx + 128] + red[tx + 192];
            float zn = fmaxf(fsqrt_a(zs), 1e-15f);
            float rv = 2.0f * R[col];
            float e  = fex2_a(rv * 1.44269504f);
            float ie = frcp_a(e);
            g_cols[which][col] = make_float4((e + ie) * frcp_a(zn), 2.0f * zn, 0.5f * (e - ie), 0.f);
        }
    }
}

// ---------------------------------------------------------------------------
// Kernel 1: tf32 GEMM, cp.async 2-stage pipeline (pre-converted inputs),
// fused Poincare epilogue (norms from global).
// ---------------------------------------------------------------------------
#define GEMM_STAGE_A (128*36)
#define GEMM_STAGE_B (32*136)
#define GEMM_SMEM_WORDS (2*GEMM_STAGE_A + 2*GEMM_STAGE_B)
__global__ __launch_bounds__(256, 2)
void gemm_proj_kernel() {
    int which = blockIdx.z;
    const unsigned* Xt = g_xt;
    const unsigned* Zt = g_zt[which];
    float* Cw = g_qkv[which];

    extern __shared__ unsigned gsm[];
    unsigned (*As)[128][36] = (unsigned(*)[128][36])gsm;
    unsigned (*Bs)[32][136] = (unsigned(*)[32][136])(gsm + 2 * GEMM_STAGE_A);
    unsigned sbase = (unsigned)__cvta_generic_to_shared(gsm);
    unsigned sa = sbase, sb = sbase + 2 * GEMM_STAGE_A * 4;

    int t = threadIdx.x;
    int wid = t >> 5, lane = t & 31;
    int L2 = lane >> 2, L0 = lane & 3;
    int wm = wid >> 1, wn = wid & 1;
    int m0 = blockIdx.x * 128, n0 = blockIdx.y * 128;

    // per-thread copy coords (8 x 16B per tile)
    int am[4], ak[4], bk[4], bn[4];
    #pragma unroll
    for (int j = 0; j < 4; j++) {
        int idx = t + j * 256;
        am[j] = idx >> 3; ak[j] = (idx & 7) * 4;
        bk[j] = idx >> 5; bn[j] = (idx & 31) * 4;
    }

    float acc[2][8][4] = {};

    // prologue: tile 0 -> stage 0
    #pragma unroll
    for (int j = 0; j < 4; j++) {
        cp16(sa + ((0 * 128 + am[j]) * 36 + ak[j]) * 4, &Xt[(m0 + am[j]) * DM + ak[j]]);
        cp16(sb + ((0 * 32 + bk[j]) * 136 + bn[j]) * 4, &Zt[bk[j] * DM + n0 + bn[j]]);
    }
    asm volatile("cp.async.commit_group;");

    #pragma unroll 1
    for (int kt = 0; kt < 32; kt++) {
        int st = kt & 1;
        asm volatile("cp.async.wait_group 0;");
        __syncthreads();
        if (kt + 1 < 32) {
            int k0 = (kt + 1) * 32, s2 = st ^ 1;
            #pragma unroll
            for (int j = 0; j < 4; j++) {
                cp16(sa + ((s2 * 128 + am[j]) * 36 + ak[j]) * 4, &Xt[(m0 + am[j]) * DM + k0 + ak[j]]);
                cp16(sb + ((s2 * 32 + bk[j]) * 136 + bn[j]) * 4, &Zt[(k0 + bk[j]) * DM + n0 + bn[j]]);
            }
            asm volatile("cp.async.commit_group;");
        }
        #pragma unroll
        for (int k8 = 0; k8 < 4; k8++) {
            int kb = k8 * 8 + L0;
            unsigned a[2][4];
            #pragma unroll
            for (int mt = 0; mt < 2; mt++) {
                int r = wm * 32 + mt * 16 + L2;
                a[mt][0] = As[st][r][kb];     a[mt][1] = As[st][r + 8][kb];
                a[mt][2] = As[st][r][kb + 4]; a[mt][3] = As[st][r + 8][kb + 4];
            }
            #pragma unroll
            for (int nt = 0; nt < 8; nt++) {
                int c = wn * 64 + nt * 8 + L2;
                unsigned b[2] = { Bs[st][kb][c], Bs[st][kb + 4][c] };
                mma8(acc[0][nt], a[0], b);
                mma8(acc[1][nt], a[1], b);
            }
        }
    }

    // ---- fused Poincare epilogue (scalars from L2-resident globals) ----
    int head = (n0 >> 6) + wn;
    #pragma unroll
    for (int mt = 0; mt < 2; mt++) {
        #pragma unroll
        for (int hh = 0; hh < 2; hh++) {
            int rloc = wm * 32 + mt * 16 + hh * 8 + L2;
            float cx2 = g_rowsq[m0 + rloc];
            float invden = frcp_a(fmaxf(1.0f - cx2, 1e-15f));
            float opc = 1.0f + cx2;
            float sq = 0.f;
            #pragma unroll
            for (int nt = 0; nt < 8; nt++) {
                int cl = wn * 64 + nt * 8 + 2 * L0;
                float4 cs0 = g_cols[which][n0 + cl];
                float4 cs1 = g_cols[which][n0 + cl + 1];
                #pragma unroll
                for (int u = 0; u < 2; u++) {
                    float4 cs = u ? cs1 : cs0;
                    float xz  = acc[mt][nt][hh * 2 + u];
                    float arg = fmaf(xz, cs.x, -opc * cs.z) * invden;
                    float aa  = fabsf(arg);
                    float A   = aa + fsqrt_a(fmaf(aa, aa, 1.0f));
                    float tE  = fex2_a(cs.y * flg2_a(A));
                    float y   = copysignf(0.5f * (tE - frcp_a(tE)), arg);
                    acc[mt][nt][hh * 2 + u] = y;
                    sq = fmaf(y, y, sq);
                }
            }
            sq += __shfl_xor_sync(0xffffffffu, sq, 1);
            sq += __shfl_xor_sync(0xffffffffu, sq, 2);
            float n1  = fmaxf(sqrtf(sq), 1e-15f);
            float s1  = (n1 > MAXN) ? (MAXN / n1) : 1.0f;
            float n1c = n1 * s1;
            float f   = 1.0f / (1.0f + sqrtf(1.0f + n1c * n1c));
            float n2  = fmaxf(n1c * f, 1e-15f);
            float s2v = (n2 > MAXN) ? (MAXN / n2) : 1.0f;
            float hs  = s1 * f * s2v;
            float n3  = n2 * s2v;
            int grow = m0 + rloc;
            if (L0 == 0) g_aux[which][grow * NH + head] = n3 * n3;
            #pragma unroll
            for (int nt = 0; nt < 8; nt++) {
                int cl = wn * 64 + nt * 8 + 2 * L0;
                *(float2*)&Cw[grow * DM + n0 + cl] =
                    make_float2(acc[mt][nt][hh * 2] * hs, acc[mt][nt][hh * 2 + 1] * hs);
            }
        }
    }
}

// ---------------------------------------------------------------------------
// Kernel 2: one-shot fragment prep for K / gamma*V (unchanged from R7)
// ---------------------------------------------------------------------------
__global__ __launch_bounds__(256)
void frag_prep_kernel(const float* __restrict__ mask) {
    __shared__ float Ks[64][68];
    __shared__ float Vs[64][68];

    int bh = blockIdx.x, kt = blockIdx.y;
    int b = bh >> 4, h = bh & 15;
    int kj0 = kt * 64;
    int t = threadIdx.x, lane = t & 31;
    int L2 = lane >> 2, L0 = lane & 3;
    int k8 = t >> 5;

    const float* K = g_qkv[1];
    const float* V = g_qkv[2];

    #pragma unroll
    for (int j = 0; j < 4; j++) {
        int idx = t + j * 256;
        int row = idx >> 4, c4 = (idx & 15) * 4;
        int gr = b * SS + kj0 + row;
        *(float4*)&Ks[row][c4] = *(const float4*)&K[gr * DM + h * DH + c4];
        float v2 = g_aux[2][gr * NH + h];
        float gam = 2.0f * frcp_a(fmaxf(1.0f - v2, 1e-15f));
        float4 vv = *(const float4*)&V[gr * DM + h * DH + c4];
        *(float4*)&Vs[row][c4] = make_float4(vv.x * gam, vv.y * gam, vv.z * gam, vv.w * gam);
    }
    if (t < 64) {
        int gr = b * SS + kj0 + t;
        float k2 = g_aux[1][gr * NH + h];
        float v2 = g_aux[2][gr * NH + h];
        g_sck[bh * 1024 + kj0 + t] =
            make_float4(k2, frcp_a(fmaxf(1.0f - k2, 1e-15f)),
                        2.0f * frcp_a(fmaxf(1.0f - v2, 1e-15f)) - 1.0f,
                        __expf(mask[b * SS + kj0 + t]));
    }
    __syncthreads();

    unsigned wk[16], wv[16];
    #pragma unroll
    for (int nt = 0; nt < 8; nt++) {
        wk[2*nt]   = f2tf32(Ks[nt * 8 + L2][k8 * 8 + L0]);
        wk[2*nt+1] = f2tf32(Ks[nt * 8 + L2][k8 * 8 + L0 + 4]);
        wv[2*nt]   = f2tf32(Vs[k8 * 8 + L0][nt * 8 + L2]);
        wv[2*nt+1] = f2tf32(Vs[k8 * 8 + L0 + 4][nt * 8 + L2]);
    }
    unsigned base = (((unsigned)(bh * 16 + kt) * 8) + k8) * 512 + lane * 4;
    #pragma unroll
    for (int i4 = 0; i4 < 4; i4++) {
        *(uint4*)&g_kfrag[base + i4 * 128] = ((uint4*)wk)[i4];
        *(uint4*)&g_vfrag[base + i4 * 128] = ((uint4*)wv)[i4];
    }
}

// ---------------------------------------------------------------------------
// Kernel 3: flash-style hyperbolic attention (unchanged from R7)
// ---------------------------------------------------------------------------
#define ATT_SMEM_WORDS (8192 + 128*68 + 8*64*4 + 128)
__global__ __launch_bounds__(256, 2)
void attn_kernel(float* __restrict__ out) {
    extern __shared__ unsigned smu[];
    unsigned* qf = smu;
    unsigned (*ps)[68] = (unsigned(*)[68])(smu + 8192);
    float4* sws = (float4*)(smu + 8192 + 128*68);
    float* q2s  = (float*)(smu + 8192 + 128*68 + 8*64*4);

    int bh = blockIdx.x, qt = blockIdx.y;
    int b = bh >> 4, h = bh & 15;
    int t = threadIdx.x, wid = t >> 5, lane = t & 31;
    int L2 = lane >> 2, L0 = lane & 3;
    int qi0 = qt * 128;

    const float* Q = g_qkv[0];

    #pragma unroll
    for (int j = 0; j < 8; j++) {
        int idx = t + j * 256;
        int row = idx >> 4, c4 = (idx & 15) * 4;
        float4 v = *(const float4*)&Q[(b * SS + qi0 + row) * DM + h * DH + c4];
        int rb = row >> 4, rr = row & 15;
        int pos = (rr >> 3) + ((c4 & 4) ? 2 : 0);
        unsigned* qb = qf + ((rb * 8 + (c4 >> 3)) * 32 + (rr & 7) * 4) * 4 + pos;
        qb[0]  = f2tf32(v.x); qb[4]  = f2tf32(v.y);
        qb[8]  = f2tf32(v.z); qb[12] = f2tf32(v.w);
    }
    if (t < 128) q2s[t] = g_aux[0][(b * SS + qi0 + t) * NH + h];
    __syncthreads();

    int rA = wid * 16 + L2;
    float q2_0 = q2s[rA], q2_1 = q2s[rA + 8];
    float tiq0 = 2.0f * frcp_a(fmaxf(1.0f - q2_0, 1e-15f));
    float tiq1 = 2.0f * frcp_a(fmaxf(1.0f - q2_1, 1e-15f));

    float4* swsW = sws + wid * 64;
    const float4* sckB = g_sck + bh * 1024;

    float o[8][4] = {};
    float accd0 = 0.f, accd1 = 0.f;

    for (int kt = 0; kt < SS / 64; kt++) {
        int kj0 = kt * 64;
        size_t fb = (size_t)((unsigned)(bh * 16 + kt) * 8) * 512 + lane * 4;
        const unsigned* kfb = g_kfrag + fb;
        const unsigned* vfb = g_vfrag + fb;

        swsW[lane * 2]     = sckB[kj0 + lane * 2];
        swsW[lane * 2 + 1] = sckB[kj0 + lane * 2 + 1];
        __syncwarp();

        float s[8][4] = {};
        #pragma unroll
        for (int k8 = 0; k8 < 8; k8++) {
            uint4 af = *(uint4*)&qf[((wid * 8 + k8) * 32 + lane) * 4];
            unsigned a[4] = { af.x, af.y, af.z, af.w };
            unsigned kw[16];
            #pragma unroll
            for (int i4 = 0; i4 < 4; i4++)
                *(uint4*)&kw[i4 * 4] = *(const uint4*)&kfb[k8 * 512 + i4 * 128];
            #pragma unroll
            for (int nt = 0; nt < 8; nt++) mma8(s[nt], a, &kw[nt * 2]);
        }

        #pragma unroll
        for (int nt = 0; nt < 8; nt++) {
            int j0 = nt * 8 + 2 * L0;
            float4 c0 = swsW[j0], c1 = swsW[j0 + 1];
            float w[4];
            #pragma unroll
            for (int e = 0; e < 4; e++) {
                float q2v = (e < 2) ? q2_0 : q2_1;
                float cc  = ((e < 2) ? tiq0 : tiq1) * ((e & 1) ? c1.y : c0.y);
                float k2v = (e & 1) ? c1.x : c0.x;
                float emv = (e & 1) ? c1.w : c0.w;
                float num = fmaxf(fmaf(-2.0f, s[nt][e], q2v + k2v), 1e-15f);
                float tt  = num * cc;
                float sr  = fsqrt_a(tt * (tt + 2.0f));
                w[e] = __fdividef(emv, (1.0f + tt) + sr);
            }
            accd0 = fmaf(w[0], c0.z, fmaf(w[1], c1.z, accd0));
            accd1 = fmaf(w[2], c0.z, fmaf(w[3], c1.z, accd1));
            *(uint2*)&ps[rA][j0]     = make_uint2(f2tf32(w[0]), f2tf32(w[1]));
            *(uint2*)&ps[rA + 8][j0] = make_uint2(f2tf32(w[2]), f2tf32(w[3]));
        }
        __syncwarp();

        #pragma unroll
        for (int k8 = 0; k8 < 8; k8++) {
            int kb = k8 * 8 + L0;
            unsigned a[4] = { ps[rA][kb], ps[rA + 8][kb], ps[rA][kb + 4], ps[rA + 8][kb + 4] };
            unsigned vw[16];
            #pragma unroll
            for (int i4 = 0; i4 < 4; i4++)
                *(uint4*)&vw[i4 * 4] = *(const uint4*)&vfb[k8 * 512 + i4 * 128];
            #pragma unroll
            for (int nt = 0; nt < 8; nt++) mma8(o[nt], a, &vw[nt * 2]);
        }
        __syncwarp();
    }

    accd0 += __shfl_xor_sync(0xffffffffu, accd0, 1);
    accd0 += __shfl_xor_sync(0xffffffffu, accd0, 2);
    accd1 += __shfl_xor_sync(0xffffffffu, accd1, 1);
    accd1 += __shfl_xor_sync(0xffffffffu, accd1, 2);
    #pragma unroll
    for (int rh = 0; rh < 2; rh++) {
        float accd = rh ? accd1 : accd0;
        float invd = 1.0f / fmaxf(accd, 1e-10f);
        float tm[8][2];
        float sq = 0.f;
        #pragma unroll
        for (int nt = 0; nt < 8; nt++) {
            tm[nt][0] = o[nt][rh * 2 + 0] * invd;
            tm[nt][1] = o[nt][rh * 2 + 1] * invd;
            sq += tm[nt][0] * tm[nt][0] + tm[nt][1] * tm[nt][1];
        }
        sq += __shfl_xor_sync(0xffffffffu, sq, 1);
        sq += __shfl_xor_sync(0xffffffffu, sq, 2);
        float f = 1.0f / (1.0f + sqrtf(fmaxf(1.0f - sq, 1e-15f)));
        float n = fmaxf(sqrtf(sq) * f, 1e-15f);
        float s2 = (n > MAXN) ? (MAXN / n) : 1.0f;
        float g = f * s2;
        int qrow = qi0 + rA + rh * 8;
        #pragma unroll
        for (int nt = 0; nt < 8; nt++) {
            *(float2*)&out[(b * SS + qrow) * DM + h * DH + nt * 8 + 2 * L0] =
                make_float2(tm[nt][0] * g, tm[nt][1] * g);
        }
    }
}

// ---------------------------------------------------------------------------
extern "C" void kernel_launch(void* const* d_in, const int* in_sizes, int n_in,
                              void* d_out, int out_size) {
    const float* hidden = (const float*)d_in[0];
    const float* amask  = (const float*)d_in[1];
    const float* qz = (const float*)d_in[2];
    const float* qr = (const float*)d_in[3];
    const float* kz = (const float*)d_in[4];
    const float* kr = (const float*)d_in[5];
    const float* vz = (const float*)d_in[6];
    const float* vr = (const float*)d_in[7];
    float* out = (float*)d_out;

    static bool attr_done = false;
    if (!attr_done) {
        cudaFuncSetAttribute(attn_kernel, cudaFuncAttributeMaxDynamicSharedMemorySize,
                             ATT_SMEM_WORDS * 4);
        cudaFuncSetAttribute(gemm_proj_kernel, cudaFuncAttributeMaxDynamicSharedMemorySize,
                             GEMM_SMEM_WORDS * 4);
        attr_done = true;
    }

    cvt_norm_kernel<<<304, 256>>>(hidden, qz, kz, vz, qr, kr, vr);
    gemm_proj_kernel<<<dim3(MROWS / 128, DM / 128, 3), 256, GEMM_SMEM_WORDS * 4>>>();
    frag_prep_kernel<<<dim3(32, 16), 256>>>(amask);
    attn_kernel<<<dim3(BB * NH, SS / 128), 256, ATT_SMEM_WORDS * 4>>>(out);
}

// round 9
// speedup vs baseline: 1.2181x; 1.2181x over previous
#include <cuda_runtime.h>
#include <math.h>

#define BB 2
#define SS 1024
#define DM 1024
#define NH 16
#define DH 64
#define MROWS (BB*SS)
#define MAXN 0.996f

__device__ float g_qkv[3][MROWS*DM];
__device__ float g_aux[3][MROWS*NH];        // per-(row,head) final ||y||^2
__device__ unsigned g_kfrag[32*16*8*512];   // K  mma-frag order
__device__ unsigned g_vfrag[32*16*8*512];   // gamma*V mma-frag order
__device__ float4   g_sck[32*1024];         // per (bh,key): {k2, 1/(1-k2), gm1, e^mask}
__device__ unsigned g_xt[MROWS*DM];         // tf32(X)
__device__ unsigned g_zt[3][DM*DM];         // tf32(Z)
__device__ float    g_rowsq[MROWS];         // ||x_row||^2
__device__ float    g_colpart[3][128][DM];  // per-rowblock col-norm partials
__device__ float4   g_cols[3][DM];          // {2cosh(2r)/zn, 2zn, sinh(2r), 0}

__device__ __forceinline__ unsigned f2tf32(float x) {
    unsigned r; asm("cvt.rna.tf32.f32 %0, %1;" : "=r"(r) : "f"(x)); return r;
}
__device__ __forceinline__ void mma8(float* d, const unsigned* a, const unsigned* b) {
    asm volatile("mma.sync.aligned.m16n8k8.row.col.f32.tf32.tf32.f32 "
        "{%0,%1,%2,%3}, {%4,%5,%6,%7}, {%8,%9}, {%0,%1,%2,%3};"
        : "+f"(d[0]), "+f"(d[1]), "+f"(d[2]), "+f"(d[3])
        : "r"(a[0]), "r"(a[1]), "r"(a[2]), "r"(a[3]), "r"(b[0]), "r"(b[1]));
}
__device__ __forceinline__ float fsqrt_a(float x){float r;asm("sqrt.approx.f32 %0,%1;":"=f"(r):"f"(x));return r;}
__device__ __forceinline__ float frcp_a (float x){float r;asm("rcp.approx.f32 %0,%1;" :"=f"(r):"f"(x));return r;}
__device__ __forceinline__ float flg2_a (float x){float r;asm("lg2.approx.f32 %0,%1;" :"=f"(r):"f"(x));return r;}
__device__ __forceinline__ float fex2_a (float x){float r;asm("ex2.approx.f32 %0,%1;" :"=f"(r):"f"(x));return r;}

// ---------------------------------------------------------------------------
// Kernel 0: convert X,Z to tf32 (row-parallel, full-chip) + norm partials.
// blocks 0..255: X (8 rows each, 1 warp/row) + row norms.
// blocks 256..639: Z (which = (bx-256)/128, 8 rows each) + col-norm partials.
// ---------------------------------------------------------------------------
__global__ __launch_bounds__(256)
void cvt_prep_kernel(const float* __restrict__ X,
                     const float* __restrict__ qz, const float* __restrict__ kz,
                     const float* __restrict__ vz) {
    int bx = blockIdx.x, t = threadIdx.x;
    if (bx < 256) {
        int row = bx * 8 + (t >> 5), lane = t & 31;
        const float* xr = X + row * DM;
        unsigned* xo = g_xt + row * DM;
        float s = 0.f;
        #pragma unroll
        for (int i = 0; i < 8; i++) {
            float4 v = *(const float4*)&xr[(i * 32 + lane) * 4];
            s = fmaf(v.x, v.x, fmaf(v.y, v.y, fmaf(v.z, v.z, fmaf(v.w, v.w, s))));
            *(uint4*)&xo[(i * 32 + lane) * 4] =
                make_uint4(f2tf32(v.x), f2tf32(v.y), f2tf32(v.z), f2tf32(v.w));
        }
        #pragma unroll
        for (int off = 16; off > 0; off >>= 1) s += __shfl_xor_sync(0xffffffffu, s, off);
        if (lane == 0) g_rowsq[row] = s;
    } else {
        int bz = bx - 256;
        int which = bz >> 7, rblk = bz & 127;
        int r0 = rblk * 8;
        const float* Z = (which == 0) ? qz : (which == 1) ? kz : vz;
        // convert 8 rows (coalesced) while accumulating 4 column partials
        float cs[4] = {};
        #pragma unroll
        for (int rr = 0; rr < 8; rr++) {
            const float* zr = Z + (r0 + rr) * DM;
            unsigned* zo = g_zt[which] + (r0 + rr) * DM;
            #pragma unroll
            for (int j = 0; j < 1; j++) { }
            float4 v0 = *(const float4*)&zr[t * 4];
            cs[0] = fmaf(v0.x, v0.x, cs[0]); cs[1] = fmaf(v0.y, v0.y, cs[1]);
            cs[2] = fmaf(v0.z, v0.z, cs[2]); cs[3] = fmaf(v0.w, v0.w, cs[3]);
            *(uint4*)&zo[t * 4] = make_uint4(f2tf32(v0.x), f2tf32(v0.y), f2tf32(v0.z), f2tf32(v0.w));
        }
        *(float4*)&g_colpart[which][rblk][t * 4] = make_float4(cs[0], cs[1], cs[2], cs[3]);
    }
}

// ---------------------------------------------------------------------------
// Kernel 0b: finish column scalars. 12 blocks x 256 threads (3 x 1024 cols)
// ---------------------------------------------------------------------------
__global__ __launch_bounds__(256)
void col_finish_kernel(const float* __restrict__ qr, const float* __restrict__ kr,
                       const float* __restrict__ vr) {
    int gid = blockIdx.x * 256 + threadIdx.x;   // 0..3071
    int which = gid >> 10, col = gid & 1023;
    const float* R = (which == 0) ? qr : (which == 1) ? kr : vr;
    float zs = 0.f;
    #pragma unroll 16
    for (int p = 0; p < 128; p++) zs += g_colpart[which][p][col];
    float zn = fmaxf(fsqrt_a(zs), 1e-15f);
    float rv = 2.0f * R[col];
    float e  = fex2_a(rv * 1.44269504f);
    float ie = frcp_a(e);
    g_cols[which][col] = make_float4((e + ie) * frcp_a(zn), 2.0f * zn, 0.5f * (e - ie), 0.f);
}

// ---------------------------------------------------------------------------
// Kernel 1: tf32 GEMM — R7 loop structure, pre-converted inputs (no cvt, no
// norm FMAs in the hot loop), fused Poincare epilogue (scalars from global).
// ---------------------------------------------------------------------------
__global__ __launch_bounds__(256, 2)
void gemm_proj_kernel() {
    int which = blockIdx.z;
    const unsigned* Xt = g_xt;
    const unsigned* Zt = g_zt[which];
    float* Cw = g_qkv[which];

    __shared__ unsigned As[128][36];
    __shared__ unsigned Bs[32][136];

    int t = threadIdx.x;
    int wid = t >> 5, lane = t & 31;
    int L2 = lane >> 2, L0 = lane & 3;
    int wm = wid >> 1, wn = wid & 1;
    int m0 = blockIdx.x * 128, n0 = blockIdx.y * 128;

    float acc[2][8][4] = {};

    for (int k0 = 0; k0 < DM; k0 += 32) {
        #pragma unroll
        for (int j = 0; j < 4; j++) {
            int idx = t + j * 256;
            int m = idx >> 3, kc = (idx & 7) * 4;
            *(uint4*)&As[m][kc] = *(const uint4*)&Xt[(m0 + m) * DM + k0 + kc];
        }
        #pragma unroll
        for (int j = 0; j < 4; j++) {
            int idx = t + j * 256;
            int kk = idx >> 5, nn = (idx & 31) * 4;
            *(uint4*)&Bs[kk][nn] = *(const uint4*)&Zt[(k0 + kk) * DM + n0 + nn];
        }
        __syncthreads();
        #pragma unroll
        for (int k8 = 0; k8 < 4; k8++) {
            int kb = k8 * 8 + L0;
            unsigned a[2][4];
            #pragma unroll
            for (int mt = 0; mt < 2; mt++) {
                int r = wm * 32 + mt * 16 + L2;
                a[mt][0] = As[r][kb];     a[mt][1] = As[r + 8][kb];
                a[mt][2] = As[r][kb + 4]; a[mt][3] = As[r + 8][kb + 4];
            }
            #pragma unroll
            for (int nt = 0; nt < 8; nt++) {
                int c = wn * 64 + nt * 8 + L2;
                unsigned b[2] = { Bs[kb][c], Bs[kb + 4][c] };
                mma8(acc[0][nt], a[0], b);
                mma8(acc[1][nt], a[1], b);
            }
        }
        __syncthreads();
    }

    // ---- fused Poincare epilogue (scalars from L2-resident globals) ----
    int head = (n0 >> 6) + wn;
    #pragma unroll
    for (int mt = 0; mt < 2; mt++) {
        #pragma unroll
        for (int hh = 0; hh < 2; hh++) {
            int rloc = wm * 32 + mt * 16 + hh * 8 + L2;
            float cx2 = g_rowsq[m0 + rloc];
            float invden = frcp_a(fmaxf(1.0f - cx2, 1e-15f));
            float opc = 1.0f + cx2;
            float sq = 0.f;
            #pragma unroll
            for (int nt = 0; nt < 8; nt++) {
                int cl = wn * 64 + nt * 8 + 2 * L0;
                float4 cs0 = g_cols[which][n0 + cl];
                float4 cs1 = g_cols[which][n0 + cl + 1];
                #pragma unroll
                for (int u = 0; u < 2; u++) {
                    float4 cs = u ? cs1 : cs0;
                    float xz  = acc[mt][nt][hh * 2 + u];
                    float arg = fmaf(xz, cs.x, -opc * cs.z) * invden;
                    float aa  = fabsf(arg);
                    float A   = aa + fsqrt_a(fmaf(aa, aa, 1.0f));
                    float tE  = fex2_a(cs.y * flg2_a(A));
                    float y   = copysignf(0.5f * (tE - frcp_a(tE)), arg);
                    acc[mt][nt][hh * 2 + u] = y;
                    sq = fmaf(y, y, sq);
                }
            }
            sq += __shfl_xor_sync(0xffffffffu, sq, 1);
            sq += __shfl_xor_sync(0xffffffffu, sq, 2);
            float n1  = fmaxf(sqrtf(sq), 1e-15f);
            float s1  = (n1 > MAXN) ? (MAXN / n1) : 1.0f;
            float n1c = n1 * s1;
            float f   = 1.0f / (1.0f + sqrtf(1.0f + n1c * n1c));
            float n2  = fmaxf(n1c * f, 1e-15f);
            float s2v = (n2 > MAXN) ? (MAXN / n2) : 1.0f;
            float hs  = s1 * f * s2v;
            float n3  = n2 * s2v;
            int grow = m0 + rloc;
            if (L0 == 0) g_aux[which][grow * NH + head] = n3 * n3;
            #pragma unroll
            for (int nt = 0; nt < 8; nt++) {
                int cl = wn * 64 + nt * 8 + 2 * L0;
                *(float2*)&Cw[grow * DM + n0 + cl] =
                    make_float2(acc[mt][nt][hh * 2] * hs, acc[mt][nt][hh * 2 + 1] * hs);
            }
        }
    }
}

// ---------------------------------------------------------------------------
// Kernel 2: one-shot fragment prep for K / gamma*V (unchanged from R7)
// ---------------------------------------------------------------------------
__global__ __launch_bounds__(256)
void frag_prep_kernel(const float* __restrict__ mask) {
    __shared__ float Ks[64][68];
    __shared__ float Vs[64][68];

    int bh = blockIdx.x, kt = blockIdx.y;
    int b = bh >> 4, h = bh & 15;
    int kj0 = kt * 64;
    int t = threadIdx.x, lane = t & 31;
    int L2 = lane >> 2, L0 = lane & 3;
    int k8 = t >> 5;

    const float* K = g_qkv[1];
    const float* V = g_qkv[2];

    #pragma unroll
    for (int j = 0; j < 4; j++) {
        int idx = t + j * 256;
        int row = idx >> 4, c4 = (idx & 15) * 4;
        int gr = b * SS + kj0 + row;
        *(float4*)&Ks[row][c4] = *(const float4*)&K[gr * DM + h * DH + c4];
        float v2 = g_aux[2][gr * NH + h];
        float gam = 2.0f * frcp_a(fmaxf(1.0f - v2, 1e-15f));
        float4 vv = *(const float4*)&V[gr * DM + h * DH + c4];
        *(float4*)&Vs[row][c4] = make_float4(vv.x * gam, vv.y * gam, vv.z * gam, vv.w * gam);
    }
    if (t < 64) {
        int gr = b * SS + kj0 + t;
        float k2 = g_aux[1][gr * NH + h];
        float v2 = g_aux[2][gr * NH + h];
        g_sck[bh * 1024 + kj0 + t] =
            make_float4(k2, frcp_a(fmaxf(1.0f - k2, 1e-15f)),
                        2.0f * frcp_a(fmaxf(1.0f - v2, 1e-15f)) - 1.0f,
                        __expf(mask[b * SS + kj0 + t]));
    }
    __syncthreads();

    unsigned wk[16], wv[16];
    #pragma unroll
    for (int nt = 0; nt < 8; nt++) {
        wk[2*nt]   = f2tf32(Ks[nt * 8 + L2][k8 * 8 + L0]);
        wk[2*nt+1] = f2tf32(Ks[nt * 8 + L2][k8 * 8 + L0 + 4]);
        wv[2*nt]   = f2tf32(Vs[k8 * 8 + L0][nt * 8 + L2]);
        wv[2*nt+1] = f2tf32(Vs[k8 * 8 + L0 + 4][nt * 8 + L2]);
    }
    unsigned base = (((unsigned)(bh * 16 + kt) * 8) + k8) * 512 + lane * 4;
    #pragma unroll
    for (int i4 = 0; i4 < 4; i4++) {
        *(uint4*)&g_kfrag[base + i4 * 128] = ((uint4*)wk)[i4];
        *(uint4*)&g_vfrag[base + i4 * 128] = ((uint4*)wv)[i4];
    }
}

// ---------------------------------------------------------------------------
// Kernel 3: flash-style hyperbolic attention (unchanged from R7)
// ---------------------------------------------------------------------------
#define ATT_SMEM_WORDS (8192 + 128*68 + 8*64*4 + 128)
__global__ __launch_bounds__(256, 2)
void attn_kernel(float* __restrict__ out) {
    extern __shared__ unsigned smu[];
    unsigned* qf = smu;
    unsigned (*ps)[68] = (unsigned(*)[68])(smu + 8192);
    float4* sws = (float4*)(smu + 8192 + 128*68);
    float* q2s  = (float*)(smu + 8192 + 128*68 + 8*64*4);

    int bh = blockIdx.x, qt = blockIdx.y;
    int b = bh >> 4, h = bh & 15;
    int t = threadIdx.x, wid = t >> 5, lane = t & 31;
    int L2 = lane >> 2, L0 = lane & 3;
    int qi0 = qt * 128;

    const float* Q = g_qkv[0];

    #pragma unroll
    for (int j = 0; j < 8; j++) {
        int idx = t + j * 256;
        int row = idx >> 4, c4 = (idx & 15) * 4;
        float4 v = *(const float4*)&Q[(b * SS + qi0 + row) * DM + h * DH + c4];
        int rb = row >> 4, rr = row & 15;
        int pos = (rr >> 3) + ((c4 & 4) ? 2 : 0);
        unsigned* qb = qf + ((rb * 8 + (c4 >> 3)) * 32 + (rr & 7) * 4) * 4 + pos;
        qb[0]  = f2tf32(v.x); qb[4]  = f2tf32(v.y);
        qb[8]  = f2tf32(v.z); qb[12] = f2tf32(v.w);
    }
    if (t < 128) q2s[t] = g_aux[0][(b * SS + qi0 + t) * NH + h];
    __syncthreads();

    int rA = wid * 16 + L2;
    float q2_0 = q2s[rA], q2_1 = q2s[rA + 8];
    float tiq0 = 2.0f * frcp_a(fmaxf(1.0f - q2_0, 1e-15f));
    float tiq1 = 2.0f * frcp_a(fmaxf(1.0f - q2_1, 1e-15f));

    float4* swsW = sws + wid * 64;
    const float4* sckB = g_sck + bh * 1024;

    float o[8][4] = {};
    float accd0 = 0.f, accd1 = 0.f;

    for (int kt = 0; kt < SS / 64; kt++) {
        int kj0 = kt * 64;
        size_t fb = (size_t)((unsigned)(bh * 16 + kt) * 8) * 512 + lane * 4;
        const unsigned* kfb = g_kfrag + fb;
        const unsigned* vfb = g_vfrag + fb;

        swsW[lane * 2]     = sckB[kj0 + lane * 2];
        swsW[lane * 2 + 1] = sckB[kj0 + lane * 2 + 1];
        __syncwarp();

        float s[8][4] = {};
        #pragma unroll
        for (int k8 = 0; k8 < 8; k8++) {
            uint4 af = *(uint4*)&qf[((wid * 8 + k8) * 32 + lane) * 4];
            unsigned a[4] = { af.x, af.y, af.z, af.w };
            unsigned kw[16];
            #pragma unroll
            for (int i4 = 0; i4 < 4; i4++)
                *(uint4*)&kw[i4 * 4] = *(const uint4*)&kfb[k8 * 512 + i4 * 128];
            #pragma unroll
            for (int nt = 0; nt < 8; nt++) mma8(s[nt], a, &kw[nt * 2]);
        }

        #pragma unroll
        for (int nt = 0; nt < 8; nt++) {
            int j0 = nt * 8 + 2 * L0;
            float4 c0 = swsW[j0], c1 = swsW[j0 + 1];
            float w[4];
            #pragma unroll
            for (int e = 0; e < 4; e++) {
                float q2v = (e < 2) ? q2_0 : q2_1;
                float cc  = ((e < 2) ? tiq0 : tiq1) * ((e & 1) ? c1.y : c0.y);
                float k2v = (e & 1) ? c1.x : c0.x;
                float emv = (e & 1) ? c1.w : c0.w;
                float num = fmaxf(fmaf(-2.0f, s[nt][e], q2v + k2v), 1e-15f);
                float tt  = num * cc;
                float sr  = fsqrt_a(tt * (tt + 2.0f));
                w[e] = __fdividef(emv, (1.0f + tt) + sr);
            }
            accd0 = fmaf(w[0], c0.z, fmaf(w[1], c1.z, accd0));
            accd1 = fmaf(w[2], c0.z, fmaf(w[3], c1.z, accd1));
            *(uint2*)&ps[rA][j0]     = make_uint2(f2tf32(w[0]), f2tf32(w[1]));
            *(uint2*)&ps[rA + 8][j0] = make_uint2(f2tf32(w[2]), f2tf32(w[3]));
        }
        __syncwarp();

        #pragma unroll
        for (int k8 = 0; k8 < 8; k8++) {
            int kb = k8 * 8 + L0;
            unsigned a[4] = { ps[rA][kb], ps[rA + 8][kb], ps[rA][kb + 4], ps[rA + 8][kb + 4] };
            unsigned vw[16];
            #pragma unroll
            for (int i4 = 0; i4 < 4; i4++)
                *(uint4*)&vw[i4 * 4] = *(const uint4*)&vfb[k8 * 512 + i4 * 128];
            #pragma unroll
            for (int nt = 0; nt < 8; nt++) mma8(o[nt], a, &vw[nt * 2]);
        }
        __syncwarp();
    }

    accd0 += __shfl_xor_sync(0xffffffffu, accd0, 1);
    accd0 += __shfl_xor_sync(0xffffffffu, accd0, 2);
    accd1 += __shfl_xor_sync(0xffffffffu, accd1, 1);
    accd1 += __shfl_xor_sync(0xffffffffu, accd1, 2);
    #pragma unroll
    for (int rh = 0; rh < 2; rh++) {
        float accd = rh ? accd1 : accd0;
        float invd = 1.0f / fmaxf(accd, 1e-10f);
        float tm[8][2];
        float sq = 0.f;
        #pragma unroll
        for (int nt = 0; nt < 8; nt++) {
            tm[nt][0] = o[nt][rh * 2 + 0] * invd;
            tm[nt][1] = o[nt][rh * 2 + 1] * invd;
            sq += tm[nt][0] * tm[nt][0] + tm[nt][1] * tm[nt][1];
        }
        sq += __shfl_xor_sync(0xffffffffu, sq, 1);
        sq += __shfl_xor_sync(0xffffffffu, sq, 2);
        float f = 1.0f / (1.0f + sqrtf(fmaxf(1.0f - sq, 1e-15f)));
        float n = fmaxf(sqrtf(sq) * f, 1e-15f);
        float s2 = (n > MAXN) ? (MAXN / n) : 1.0f;
        float g = f * s2;
        int qrow = qi0 + rA + rh * 8;
        #pragma unroll
        for (int nt = 0; nt < 8; nt++) {
            *(float2*)&out[(b * SS + qrow) * DM + h * DH + nt * 8 + 2 * L0] =
                make_float2(tm[nt][0] * g, tm[nt][1] * g);
        }
    }
}

// ---------------------------------------------------------------------------
extern "C" void kernel_launch(void* const* d_in, const int* in_sizes, int n_in,
                              void* d_out, int out_size) {
    const float* hidden = (const float*)d_in[0];
    const float* amask  = (const float*)d_in[1];
    const float* qz = (const float*)d_in[2];
    const float* qr = (const float*)d_in[3];
    const float* kz = (const float*)d_in[4];
    const float* kr = (const float*)d_in[5];
    const float* vz = (const float*)d_in[6];
    const float* vr = (const float*)d_in[7];
    float* out = (float*)d_out;

    static bool attr_done = false;
    if (!attr_done) {
        cudaFuncSetAttribute(attn_kernel, cudaFuncAttributeMaxDynamicSharedMemorySize,
                             ATT_SMEM_WORDS * 4);
        attr_done = true;
    }

    cvt_prep_kernel<<<640, 256>>>(hidden, qz, kz, vz);
    col_finish_kernel<<<12, 256>>>(qr, kr, vr);
    gemm_proj_kernel<<<dim3(MROWS / 128, DM / 128, 3), 256>>>();
    frag_prep_kernel<<<dim3(32, 16), 256>>>(amask);
    attn_kernel<<<dim3(BB * NH, SS / 128), 256, ATT_SMEM_WORDS * 4>>>(out);
}

// round 10
// speedup vs baseline: 1.2740x; 1.0459x over previous
#include <cuda_runtime.h>
#include <math.h>

#define BB 2
#define SS 1024
#define DM 1024
#define NH 16
#define DH 64
#define MROWS (BB*SS)
#define MAXN 0.996f

__device__ float g_qkv[3][MROWS*DM];
__device__ float g_aux[3][MROWS*NH];        // per-(row,head) final ||y||^2
__device__ unsigned g_kfrag[32*16*8*512];   // K  mma-frag order
__device__ unsigned g_vfrag[32*16*8*512];   // gamma*V mma-frag order
__device__ float4   g_sck[32*1024];         // per (bh,key): {k2, 1/(1-k2), gm1, e^mask}
__device__ unsigned g_xt[MROWS*DM];         // tf32(X)
__device__ unsigned g_zt[3][DM*DM];         // tf32(Z)
__device__ float    g_rowsq[MROWS];         // ||x_row||^2
__device__ float    g_colpart[3][128][DM];  // per-rowblock col-norm partials
__device__ float4   g_cols[3][DM];          // {2cosh(2r)/zn, 2zn, sinh(2r), 0}

__device__ __forceinline__ unsigned f2tf32(float x) {
    unsigned r; asm("cvt.rna.tf32.f32 %0, %1;" : "=r"(r) : "f"(x)); return r;
}
__device__ __forceinline__ void mma8(float* d, const unsigned* a, const unsigned* b) {
    asm volatile("mma.sync.aligned.m16n8k8.row.col.f32.tf32.tf32.f32 "
        "{%0,%1,%2,%3}, {%4,%5,%6,%7}, {%8,%9}, {%0,%1,%2,%3};"
        : "+f"(d[0]), "+f"(d[1]), "+f"(d[2]), "+f"(d[3])
        : "r"(a[0]), "r"(a[1]), "r"(a[2]), "r"(a[3]), "r"(b[0]), "r"(b[1]));
}
__device__ __forceinline__ float fsqrt_a(float x){float r;asm("sqrt.approx.f32 %0,%1;":"=f"(r):"f"(x));return r;}
__device__ __forceinline__ float frcp_a (float x){float r;asm("rcp.approx.f32 %0,%1;" :"=f"(r):"f"(x));return r;}
__device__ __forceinline__ float flg2_a (float x){float r;asm("lg2.approx.f32 %0,%1;" :"=f"(r):"f"(x));return r;}
__device__ __forceinline__ float fex2_a (float x){float r;asm("ex2.approx.f32 %0,%1;" :"=f"(r):"f"(x));return r;}
__device__ __forceinline__ void cp16(unsigned s, const void* g) {
    asm volatile("cp.async.ca.shared.global [%0], [%1], 16;" :: "r"(s), "l"(g));
}

// ---------------------------------------------------------------------------
// Kernel 0: convert X,Z to tf32 (row-parallel, full-chip) + norm partials.
// (R9 proven version)
// ---------------------------------------------------------------------------
__global__ __launch_bounds__(256)
void cvt_prep_kernel(const float* __restrict__ X,
                     const float* __restrict__ qz, const float* __restrict__ kz,
                     const float* __restrict__ vz) {
    int bx = blockIdx.x, t = threadIdx.x;
    if (bx < 256) {
        int row = bx * 8 + (t >> 5), lane = t & 31;
        const float* xr = X + row * DM;
        unsigned* xo = g_xt + row * DM;
        float s = 0.f;
        #pragma unroll
        for (int i = 0; i < 8; i++) {
            float4 v = *(const float4*)&xr[(i * 32 + lane) * 4];
            s = fmaf(v.x, v.x, fmaf(v.y, v.y, fmaf(v.z, v.z, fmaf(v.w, v.w, s))));
            *(uint4*)&xo[(i * 32 + lane) * 4] =
                make_uint4(f2tf32(v.x), f2tf32(v.y), f2tf32(v.z), f2tf32(v.w));
        }
        #pragma unroll
        for (int off = 16; off > 0; off >>= 1) s += __shfl_xor_sync(0xffffffffu, s, off);
        if (lane == 0) g_rowsq[row] = s;
    } else {
        int bz = bx - 256;
        int which = bz >> 7, rblk = bz & 127;
        int r0 = rblk * 8;
        const float* Z = (which == 0) ? qz : (which == 1) ? kz : vz;
        float cs[4] = {};
        #pragma unroll
        for (int rr = 0; rr < 8; rr++) {
            const float* zr = Z + (r0 + rr) * DM;
            unsigned* zo = g_zt[which] + (r0 + rr) * DM;
            float4 v0 = *(const float4*)&zr[t * 4];
            cs[0] = fmaf(v0.x, v0.x, cs[0]); cs[1] = fmaf(v0.y, v0.y, cs[1]);
            cs[2] = fmaf(v0.z, v0.z, cs[2]); cs[3] = fmaf(v0.w, v0.w, cs[3]);
            *(uint4*)&zo[t * 4] = make_uint4(f2tf32(v0.x), f2tf32(v0.y), f2tf32(v0.z), f2tf32(v0.w));
        }
        *(float4*)&g_colpart[which][rblk][t * 4] = make_float4(cs[0], cs[1], cs[2], cs[3]);
    }
}

// ---------------------------------------------------------------------------
// Kernel 0b: finish column scalars. (R9 proven version)
// ---------------------------------------------------------------------------
__global__ __launch_bounds__(256)
void col_finish_kernel(const float* __restrict__ qr, const float* __restrict__ kr,
                       const float* __restrict__ vr) {
    int gid = blockIdx.x * 256 + threadIdx.x;   // 0..3071
    int which = gid >> 10, col = gid & 1023;
    const float* R = (which == 0) ? qr : (which == 1) ? kr : vr;
    float zs = 0.f;
    #pragma unroll 16
    for (int p = 0; p < 128; p++) zs += g_colpart[which][p][col];
    float zn = fmaxf(fsqrt_a(zs), 1e-15f);
    float rv = 2.0f * R[col];
    float e  = fex2_a(rv * 1.44269504f);
    float ie = frcp_a(e);
    g_cols[which][col] = make_float4((e + ie) * frcp_a(zn), 2.0f * zn, 0.5f * (e - ie), 0.f);
}

// ---------------------------------------------------------------------------
// Kernel 1: tf32 GEMM, cp.async 2-stage pipeline (R8 structure, exonerating
// test), fused Poincare epilogue.
// ---------------------------------------------------------------------------
#define GEMM_STAGE_A (128*36)
#define GEMM_STAGE_B (32*136)
#define GEMM_SMEM_WORDS (2*GEMM_STAGE_A + 2*GEMM_STAGE_B)
__global__ __launch_bounds__(256, 2)
void gemm_proj_kernel() {
    int which = blockIdx.z;
    const unsigned* Xt = g_xt;
    const unsigned* Zt = g_zt[which];
    float* Cw = g_qkv[which];

    extern __shared__ unsigned gsm[];
    unsigned (*As)[128][36] = (unsigned(*)[128][36])gsm;
    unsigned (*Bs)[32][136] = (unsigned(*)[32][136])(gsm + 2 * GEMM_STAGE_A);
    unsigned sbase = (unsigned)__cvta_generic_to_shared(gsm);
    unsigned sa = sbase, sb = sbase + 2 * GEMM_STAGE_A * 4;

    int t = threadIdx.x;
    int wid = t >> 5, lane = t & 31;
    int L2 = lane >> 2, L0 = lane & 3;
    int wm = wid >> 1, wn = wid & 1;
    int m0 = blockIdx.x * 128, n0 = blockIdx.y * 128;

    int am[4], ak[4], bk[4], bn[4];
    #pragma unroll
    for (int j = 0; j < 4; j++) {
        int idx = t + j * 256;
        am[j] = idx >> 3; ak[j] = (idx & 7) * 4;
        bk[j] = idx >> 5; bn[j] = (idx & 31) * 4;
    }

    float acc[2][8][4] = {};

    #pragma unroll
    for (int j = 0; j < 4; j++) {
        cp16(sa + ((0 * 128 + am[j]) * 36 + ak[j]) * 4, &Xt[(m0 + am[j]) * DM + ak[j]]);
        cp16(sb + ((0 * 32 + bk[j]) * 136 + bn[j]) * 4, &Zt[bk[j] * DM + n0 + bn[j]]);
    }
    asm volatile("cp.async.commit_group;");

    #pragma unroll 1
    for (int kt = 0; kt < 32; kt++) {
        int st = kt & 1;
        asm volatile("cp.async.wait_group 0;");
        __syncthreads();
        if (kt + 1 < 32) {
            int k0 = (kt + 1) * 32, s2 = st ^ 1;
            #pragma unroll
            for (int j = 0; j < 4; j++) {
                cp16(sa + ((s2 * 128 + am[j]) * 36 + ak[j]) * 4, &Xt[(m0 + am[j]) * DM + k0 + ak[j]]);
                cp16(sb + ((s2 * 32 + bk[j]) * 136 + bn[j]) * 4, &Zt[(k0 + bk[j]) * DM + n0 + bn[j]]);
            }
            asm volatile("cp.async.commit_group;");
        }
        #pragma unroll
        for (int k8 = 0; k8 < 4; k8++) {
            int kb = k8 * 8 + L0;
            unsigned a[2][4];
            #pragma unroll
            for (int mt = 0; mt < 2; mt++) {
                int r = wm * 32 + mt * 16 + L2;
                a[mt][0] = As[st][r][kb];     a[mt][1] = As[st][r + 8][kb];
                a[mt][2] = As[st][r][kb + 4]; a[mt][3] = As[st][r + 8][kb + 4];
            }
            #pragma unroll
            for (int nt = 0; nt < 8; nt++) {
                int c = wn * 64 + nt * 8 + L2;
                unsigned b[2] = { Bs[st][kb][c], Bs[st][kb + 4][c] };
                mma8(acc[0][nt], a[0], b);
                mma8(acc[1][nt], a[1], b);
            }
        }
    }

    // ---- fused Poincare epilogue (scalars from L2-resident globals) ----
    int head = (n0 >> 6) + wn;
    #pragma unroll
    for (int mt = 0; mt < 2; mt++) {
        #pragma unroll
        for (int hh = 0; hh < 2; hh++) {
            int rloc = wm * 32 + mt * 16 + hh * 8 + L2;
            float cx2 = g_rowsq[m0 + rloc];
            float invden = frcp_a(fmaxf(1.0f - cx2, 1e-15f));
            float opc = 1.0f + cx2;
            float sq = 0.f;
            #pragma unroll
            for (int nt = 0; nt < 8; nt++) {
                int cl = wn * 64 + nt * 8 + 2 * L0;
                float4 cs0 = g_cols[which][n0 + cl];
                float4 cs1 = g_cols[which][n0 + cl + 1];
                #pragma unroll
                for (int u = 0; u < 2; u++) {
                    float4 cs = u ? cs1 : cs0;
                    float xz  = acc[mt][nt][hh * 2 + u];
                    float arg = fmaf(xz, cs.x, -opc * cs.z) * invden;
                    float aa  = fabsf(arg);
                    float A   = aa + fsqrt_a(fmaf(aa, aa, 1.0f));
                    float tE  = fex2_a(cs.y * flg2_a(A));
                    float y   = copysignf(0.5f * (tE - frcp_a(tE)), arg);
                    acc[mt][nt][hh * 2 + u] = y;
                    sq = fmaf(y, y, sq);
                }
            }
            sq += __shfl_xor_sync(0xffffffffu, sq, 1);
            sq += __shfl_xor_sync(0xffffffffu, sq, 2);
            float n1  = fmaxf(sqrtf(sq), 1e-15f);
            float s1  = (n1 > MAXN) ? (MAXN / n1) : 1.0f;
            float n1c = n1 * s1;
            float f   = 1.0f / (1.0f + sqrtf(1.0f + n1c * n1c));
            float n2  = fmaxf(n1c * f, 1e-15f);
            float s2v = (n2 > MAXN) ? (MAXN / n2) : 1.0f;
            float hs  = s1 * f * s2v;
            float n3  = n2 * s2v;
            int grow = m0 + rloc;
            if (L0 == 0) g_aux[which][grow * NH + head] = n3 * n3;
            #pragma unroll
            for (int nt = 0; nt < 8; nt++) {
                int cl = wn * 64 + nt * 8 + 2 * L0;
                *(float2*)&Cw[grow * DM + n0 + cl] =
                    make_float2(acc[mt][nt][hh * 2] * hs, acc[mt][nt][hh * 2 + 1] * hs);
            }
        }
    }
}

// ---------------------------------------------------------------------------
// Kernel 2: one-shot fragment prep for K / gamma*V (unchanged)
// ---------------------------------------------------------------------------
__global__ __launch_bounds__(256)
void frag_prep_kernel(const float* __restrict__ mask) {
    __shared__ float Ks[64][68];
    __shared__ float Vs[64][68];

    int bh = blockIdx.x, kt = blockIdx.y;
    int b = bh >> 4, h = bh & 15;
    int kj0 = kt * 64;
    int t = threadIdx.x, lane = t & 31;
    int L2 = lane >> 2, L0 = lane & 3;
    int k8 = t >> 5;

    const float* K = g_qkv[1];
    const float* V = g_qkv[2];

    #pragma unroll
    for (int j = 0; j < 4; j++) {
        int idx = t + j * 256;
        int row = idx >> 4, c4 = (idx & 15) * 4;
        int gr = b * SS + kj0 + row;
        *(float4*)&Ks[row][c4] = *(const float4*)&K[gr * DM + h * DH + c4];
        float v2 = g_aux[2][gr * NH + h];
        float gam = 2.0f * frcp_a(fmaxf(1.0f - v2, 1e-15f));
        float4 vv = *(const float4*)&V[gr * DM + h * DH + c4];
        *(float4*)&Vs[row][c4] = make_float4(vv.x * gam, vv.y * gam, vv.z * gam, vv.w * gam);
    }
    if (t < 64) {
        int gr = b * SS + kj0 + t;
        float k2 = g_aux[1][gr * NH + h];
        float v2 = g_aux[2][gr * NH + h];
        g_sck[bh * 1024 + kj0 + t] =
            make_float4(k2, frcp_a(fmaxf(1.0f - k2, 1e-15f)),
                        2.0f * frcp_a(fmaxf(1.0f - v2, 1e-15f)) - 1.0f,
                        __expf(mask[b * SS + kj0 + t]));
    }
    __syncthreads();

    unsigned wk[16], wv[16];
    #pragma unroll
    for (int nt = 0; nt < 8; nt++) {
        wk[2*nt]   = f2tf32(Ks[nt * 8 + L2][k8 * 8 + L0]);
        wk[2*nt+1] = f2tf32(Ks[nt * 8 + L2][k8 * 8 + L0 + 4]);
        wv[2*nt]   = f2tf32(Vs[k8 * 8 + L0][nt * 8 + L2]);
        wv[2*nt+1] = f2tf32(Vs[k8 * 8 + L0 + 4][nt * 8 + L2]);
    }
    unsigned base = (((unsigned)(bh * 16 + kt) * 8) + k8) * 512 + lane * 4;
    #pragma unroll
    for (int i4 = 0; i4 < 4; i4++) {
        *(uint4*)&g_kfrag[base + i4 * 128] = ((uint4*)wk)[i4];
        *(uint4*)&g_vfrag[base + i4 * 128] = ((uint4*)wv)[i4];
    }
}

// ---------------------------------------------------------------------------
// Kernel 3: flash-style hyperbolic attention (unchanged)
// ---------------------------------------------------------------------------
#define ATT_SMEM_WORDS (8192 + 128*68 + 8*64*4 + 128)
__global__ __launch_bounds__(256, 2)
void attn_kernel(float* __restrict__ out) {
    extern __shared__ unsigned smu[];
    unsigned* qf = smu;
    unsigned (*ps)[68] = (unsigned(*)[68])(smu + 8192);
    float4* sws = (float4*)(smu + 8192 + 128*68);
    float* q2s  = (float*)(smu + 8192 + 128*68 + 8*64*4);

    int bh = blockIdx.x, qt = blockIdx.y;
    int b = bh >> 4, h = bh & 15;
    int t = threadIdx.x, wid = t >> 5, lane = t & 31;
    int L2 = lane >> 2, L0 = lane & 3;
    int qi0 = qt * 128;

    const float* Q = g_qkv[0];

    #pragma unroll
    for (int j = 0; j < 8; j++) {
        int idx = t + j * 256;
        int row = idx >> 4, c4 = (idx & 15) * 4;
        float4 v = *(const float4*)&Q[(b * SS + qi0 + row) * DM + h * DH + c4];
        int rb = row >> 4, rr = row & 15;
        int pos = (rr >> 3) + ((c4 & 4) ? 2 : 0);
        unsigned* qb = qf + ((rb * 8 + (c4 >> 3)) * 32 + (rr & 7) * 4) * 4 + pos;
        qb[0]  = f2tf32(v.x); qb[4]  = f2tf32(v.y);
        qb[8]  = f2tf32(v.z); qb[12] = f2tf32(v.w);
    }
    if (t < 128) q2s[t] = g_aux[0][(b * SS + qi0 + t) * NH + h];
    __syncthreads();

    int rA = wid * 16 + L2;
    float q2_0 = q2s[rA], q2_1 = q2s[rA + 8];
    float tiq0 = 2.0f * frcp_a(fmaxf(1.0f - q2_0, 1e-15f));
    float tiq1 = 2.0f * frcp_a(fmaxf(1.0f - q2_1, 1e-15f));

    float4* swsW = sws + wid * 64;
    const float4* sckB = g_sck + bh * 1024;

    float o[8][4] = {};
    float accd0 = 0.f, accd1 = 0.f;

    for (int kt = 0; kt < SS / 64; kt++) {
        int kj0 = kt * 64;
        size_t fb = (size_t)((unsigned)(bh * 16 + kt) * 8) * 512 + lane * 4;
        const unsigned* kfb = g_kfrag + fb;
        const unsigned* vfb = g_vfrag + fb;

        swsW[lane * 2]     = sckB[kj0 + lane * 2];
        swsW[lane * 2 + 1] = sckB[kj0 + lane * 2 + 1];
        __syncwarp();

        float s[8][4] = {};
        #pragma unroll
        for (int k8 = 0; k8 < 8; k8++) {
            uint4 af = *(uint4*)&qf[((wid * 8 + k8) * 32 + lane) * 4];
            unsigned a[4] = { af.x, af.y, af.z, af.w };
            unsigned kw[16];
            #pragma unroll
            for (int i4 = 0; i4 < 4; i4++)
                *(uint4*)&kw[i4 * 4] = *(const uint4*)&kfb[k8 * 512 + i4 * 128];
            #pragma unroll
            for (int nt = 0; nt < 8; nt++) mma8(s[nt], a, &kw[nt * 2]);
        }

        #pragma unroll
        for (int nt = 0; nt < 8; nt++) {
            int j0 = nt * 8 + 2 * L0;
            float4 c0 = swsW[j0], c1 = swsW[j0 + 1];
            float w[4];
            #pragma unroll
            for (int e = 0; e < 4; e++) {
                float q2v = (e < 2) ? q2_0 : q2_1;
                float cc  = ((e < 2) ? tiq0 : tiq1) * ((e & 1) ? c1.y : c0.y);
                float k2v = (e & 1) ? c1.x : c0.x;
                float emv = (e & 1) ? c1.w : c0.w;
                float num = fmaxf(fmaf(-2.0f, s[nt][e], q2v + k2v), 1e-15f);
                float tt  = num * cc;
                float sr  = fsqrt_a(tt * (tt + 2.0f));
                w[e] = __fdividef(emv, (1.0f + tt) + sr);
            }
            accd0 = fmaf(w[0], c0.z, fmaf(w[1], c1.z, accd0));
            accd1 = fmaf(w[2], c0.z, fmaf(w[3], c1.z, accd1));
            *(uint2*)&ps[rA][j0]     = make_uint2(f2tf32(w[0]), f2tf32(w[1]));
            *(uint2*)&ps[rA + 8][j0] = make_uint2(f2tf32(w[2]), f2tf32(w[3]));
        }
        __syncwarp();

        #pragma unroll
        for (int k8 = 0; k8 < 8; k8++) {
            int kb = k8 * 8 + L0;
            unsigned a[4] = { ps[rA][kb], ps[rA + 8][kb], ps[rA][kb + 4], ps[rA + 8][kb + 4] };
            unsigned vw[16];
            #pragma unroll
            for (int i4 = 0; i4 < 4; i4++)
                *(uint4*)&vw[i4 * 4] = *(const uint4*)&vfb[k8 * 512 + i4 * 128];
            #pragma unroll
            for (int nt = 0; nt < 8; nt++) mma8(o[nt], a, &vw[nt * 2]);
        }
        __syncwarp();
    }

    accd0 += __shfl_xor_sync(0xffffffffu, accd0, 1);
    accd0 += __shfl_xor_sync(0xffffffffu, accd0, 2);
    accd1 += __shfl_xor_sync(0xffffffffu, accd1, 1);
    accd1 += __shfl_xor_sync(0xffffffffu, accd1, 2);
    #pragma unroll
    for (int rh = 0; rh < 2; rh++) {
        float accd = rh ? accd1 : accd0;
        float invd = 1.0f / fmaxf(accd, 1e-10f);
        float tm[8][2];
        float sq = 0.f;
        #pragma unroll
        for (int nt = 0; nt < 8; nt++) {
            tm[nt][0] = o[nt][rh * 2 + 0] * invd;
            tm[nt][1] = o[nt][rh * 2 + 1] * invd;
            sq += tm[nt][0] * tm[nt][0] + tm[nt][1] * tm[nt][1];
        }
        sq += __shfl_xor_sync(0xffffffffu, sq, 1);
        sq += __shfl_xor_sync(0xffffffffu, sq, 2);
        float f = 1.0f / (1.0f + sqrtf(fmaxf(1.0f - sq, 1e-15f)));
        float n = fmaxf(sqrtf(sq) * f, 1e-15f);
        float s2 = (n > MAXN) ? (MAXN / n) : 1.0f;
        float g = f * s2;
        int qrow = qi0 + rA + rh * 8;
        #pragma unroll
        for (int nt = 0; nt < 8; nt++) {
            *(float2*)&out[(b * SS + qrow) * DM + h * DH + nt * 8 + 2 * L0] =
                make_float2(tm[nt][0] * g, tm[nt][1] * g);
        }
    }
}

// ---------------------------------------------------------------------------
extern "C" void kernel_launch(void* const* d_in, const int* in_sizes, int n_in,
                              void* d_out, int out_size) {
    const float* hidden = (const float*)d_in[0];
    const float* amask  = (const float*)d_in[1];
    const float* qz = (const float*)d_in[2];
    const float* qr = (const float*)d_in[3];
    const float* kz = (const float*)d_in[4];
    const float* kr = (const float*)d_in[5];
    const float* vz = (const float*)d_in[6];
    const float* vr = (const float*)d_in[7];
    float* out = (float*)d_out;

    static bool attr_done = false;
    if (!attr_done) {
        cudaFuncSetAttribute(attn_kernel, cudaFuncAttributeMaxDynamicSharedMemorySize,
                             ATT_SMEM_WORDS * 4);
        cudaFuncSetAttribute(gemm_proj_kernel, cudaFuncAttributeMaxDynamicSharedMemorySize,
                             GEMM_SMEM_WORDS * 4);
        attr_done = true;
    }

    cvt_prep_kernel<<<640, 256>>>(hidden, qz, kz, vz);
    col_finish_kernel<<<12, 256>>>(qr, kr, vr);
    gemm_proj_kernel<<<dim3(MROWS / 128, DM / 128, 3), 256, GEMM_SMEM_WORDS * 4>>>();
    frag_prep_kernel<<<dim3(32, 16), 256>>>(amask);
    attn_kernel<<<dim3(BB * NH, SS / 128), 256, ATT_SMEM_WORDS * 4>>>(out);
}

// round 12
// speedup vs baseline: 1.9761x; 1.5510x over previous
#include <cuda_runtime.h>
#include <cuda_fp16.h>
#include <math.h>

#define BB 2
#define SS 1024
#define DM 1024
#define NH 16
#define DH 64
#define MROWS (BB*SS)
#define MAXN 0.996f

__device__ float g_qkv[3][MROWS*DM];
__device__ float g_aux[3][MROWS*NH];        // per-(row,head) final ||y||^2
__device__ unsigned g_kfrag[32*16*4*512];   // K  fp16 mma-frag order
__device__ unsigned g_vfrag[32*16*4*512];   // gamma*V fp16 mma-frag order
__device__ float4   g_sck[32*1024];         // per (bh,key): {k2, 1/(1-k2), gm1, e^mask}
__device__ unsigned g_xh[MROWS*DM/2];       // fp16x2(X)   [m][k/2]
__device__ unsigned g_zhT[3][DM*DM/2];      // fp16x2(Z^T) [n][k/2]
__device__ float    g_rowsq[MROWS];         // ||x_row||^2
__device__ float    g_colpart[3][16][DM];   // per-ktile col-norm partials
__device__ float4   g_cols[3][DM];          // {2cosh(2r)/zn, 2zn, sinh(2r), 0}

__device__ __forceinline__ unsigned packh2(float lo, float hi) {
    __half2 h = __floats2half2_rn(lo, hi);
    return *(unsigned*)&h;
}
__device__ __forceinline__ void mma16(float* d, const unsigned* a, const unsigned* b) {
    asm volatile("mma.sync.aligned.m16n8k16.row.col.f32.f16.f16.f32 "
        "{%0,%1,%2,%3}, {%4,%5,%6,%7}, {%8,%9}, {%0,%1,%2,%3};"
        : "+f"(d[0]), "+f"(d[1]), "+f"(d[2]), "+f"(d[3])
        : "r"(a[0]), "r"(a[1]), "r"(a[2]), "r"(a[3]), "r"(b[0]), "r"(b[1]));
}
__device__ __forceinline__ float fsqrt_a(float x){float r;asm("sqrt.approx.f32 %0,%1;":"=f"(r):"f"(x));return r;}
__device__ __forceinline__ float frcp_a (float x){float r;asm("rcp.approx.f32 %0,%1;" :"=f"(r):"f"(x));return r;}
__device__ __forceinline__ float flg2_a (float x){float r;asm("lg2.approx.f32 %0,%1;" :"=f"(r):"f"(x));return r;}
__device__ __forceinline__ float fex2_a (float x){float r;asm("ex2.approx.f32 %0,%1;" :"=f"(r):"f"(x));return r;}
__device__ __forceinline__ void cp16(unsigned s, const void* g) {
    asm volatile("cp.async.ca.shared.global [%0], [%1], 16;" :: "r"(s), "l"(g));
}

// ---------------------------------------------------------------------------
// Kernel 0a: X -> fp16 + row norms
// ---------------------------------------------------------------------------
__global__ __launch_bounds__(256)
void xcvt_kernel(const float* __restrict__ X) {
    int row = blockIdx.x * 8 + (threadIdx.x >> 5), lane = threadIdx.x & 31;
    const float* xr = X + row * DM;
    unsigned* xo = g_xh + row * (DM / 2);
    float s = 0.f;
    #pragma unroll
    for (int i = 0; i < 8; i++) {
        float4 v = *(const float4*)&xr[(i * 32 + lane) * 4];
        s = fmaf(v.x, v.x, fmaf(v.y, v.y, fmaf(v.z, v.z, fmaf(v.w, v.w, s))));
        *(uint2*)&xo[(i * 32 + lane) * 2] = make_uint2(packh2(v.x, v.y), packh2(v.z, v.w));
    }
    #pragma unroll
    for (int off = 16; off > 0; off >>= 1) s += __shfl_xor_sync(0xffffffffu, s, off);
    if (lane == 0) g_rowsq[row] = s;
}

// ---------------------------------------------------------------------------
// Kernel 0b: Z -> fp16 TRANSPOSED ([n][k]) via 64x64 smem tiles + col partials
// ---------------------------------------------------------------------------
__global__ __launch_bounds__(256)
void ztrans_kernel(const float* __restrict__ qz, const float* __restrict__ kz,
                   const float* __restrict__ vz) {
    __shared__ float tile[64][65];
    __shared__ float redc[16][64];
    int which = blockIdx.z;
    int k0 = blockIdx.x * 64, n0 = blockIdx.y * 64;
    const float* Z = (which == 0) ? qz : (which == 1) ? kz : vz;
    int t = threadIdx.x;
    float cp0 = 0.f, cp1 = 0.f, cp2 = 0.f, cp3 = 0.f;
    #pragma unroll
    for (int j = 0; j < 4; j++) {
        int idx = t + j * 256;
        int r = idx >> 4, c4 = (idx & 15) * 4;
        float4 v = *(const float4*)&Z[(k0 + r) * DM + n0 + c4];
        tile[r][c4] = v.x; tile[r][c4 + 1] = v.y;
        tile[r][c4 + 2] = v.z; tile[r][c4 + 3] = v.w;
        cp0 = fmaf(v.x, v.x, cp0); cp1 = fmaf(v.y, v.y, cp1);
        cp2 = fmaf(v.z, v.z, cp2); cp3 = fmaf(v.w, v.w, cp3);
    }
    int cg = (t & 15) * 4;
    redc[t >> 4][cg] = cp0; redc[t >> 4][cg + 1] = cp1;
    redc[t >> 4][cg + 2] = cp2; redc[t >> 4][cg + 3] = cp3;
    __syncthreads();
    if (t < 64) {
        float s = 0.f;
        #pragma unroll
        for (int g = 0; g < 16; g++) s += redc[g][t];
        g_colpart[which][blockIdx.x][n0 + t] = s;
    }
    #pragma unroll
    for (int j = 0; j < 4; j++) {
        int idx = t + j * 256;
        int nr = idx >> 4, kc4 = (idx & 15) * 4;
        *(uint2*)&g_zhT[which][(n0 + nr) * (DM / 2) + (k0 + kc4) / 2] =
            make_uint2(packh2(tile[kc4][nr], tile[kc4 + 1][nr]),
                       packh2(tile[kc4 + 2][nr], tile[kc4 + 3][nr]));
    }
}

// ---------------------------------------------------------------------------
// Kernel 0c: finish column scalars (sum 16 partials)
// ---------------------------------------------------------------------------
__global__ __launch_bounds__(256)
void col_finish_kernel(const float* __restrict__ qr, const float* __restrict__ kr,
                       const float* __restrict__ vr) {
    int gid = blockIdx.x * 256 + threadIdx.x;   // 0..3071
    int which = gid >> 10, col = gid & 1023;
    const float* R = (which == 0) ? qr : (which == 1) ? kr : vr;
    float zs = 0.f;
    #pragma unroll
    for (int p = 0; p < 16; p++) zs += g_colpart[which][p][col];
    float zn = fmaxf(fsqrt_a(zs), 1e-15f);
    float rv = 2.0f * R[col];
    float e  = fex2_a(rv * 1.44269504f);
    float ie = frcp_a(e);
    g_cols[which][col] = make_float4((e + ie) * frcp_a(zn), 2.0f * zn, 0.5f * (e - ie), 0.f);
}

// ---------------------------------------------------------------------------
// Kernel 1: fp16 m16n8k16 GEMM, cp.async 2-stage pipeline, BK=64, fused
// Poincare epilogue. A [m][k] fp16x2, B = Z^T [n][k] fp16x2 (row.col mma).
// ---------------------------------------------------------------------------
#define GEMM_STAGE (128*36)                    // uints per stage per operand
#define GEMM_SMEM_WORDS (4*GEMM_STAGE)
__global__ __launch_bounds__(256, 2)
void gemm_proj_kernel() {
    int which = blockIdx.z;
    const unsigned* Xh = g_xh;
    const unsigned* Zh = g_zhT[which];
    float* Cw = g_qkv[which];

    extern __shared__ unsigned gsm[];
    unsigned (*As)[128][36] = (unsigned(*)[128][36])gsm;
    unsigned (*Bs)[128][36] = (unsigned(*)[128][36])(gsm + 2 * GEMM_STAGE);
    unsigned sbase = (unsigned)__cvta_generic_to_shared(gsm);
    unsigned sa = sbase, sb = sbase + 2 * GEMM_STAGE * 4;

    int t = threadIdx.x;
    int wid = t >> 5, lane = t & 31;
    int L2 = lane >> 2, L0 = lane & 3;
    int wm = wid >> 1, wn = wid & 1;
    int m0 = blockIdx.x * 128, n0 = blockIdx.y * 128;

    float acc[2][8][4] = {};

    // per-tile copy: 128 rows x 8 segs (16B) for each operand; 4+4 per thread
#define G_PREFETCH(kc, sg) do {                                               \
        _Pragma("unroll")                                                     \
        for (int j_ = 0; j_ < 4; j_++) {                                      \
            int u_ = t + j_ * 256;                                            \
            int row_ = u_ >> 3, seg_ = u_ & 7;                                \
            unsigned off_ = (((unsigned)(sg) * 128 + row_) * 36 + seg_ * 4) * 4; \
            cp16(sa + off_, &Xh[(m0 + row_) * (DM/2) + (kc) * 32 + seg_ * 4]); \
            cp16(sb + off_, &Zh[(n0 + row_) * (DM/2) + (kc) * 32 + seg_ * 4]); \
        }                                                                     \
        asm volatile("cp.async.commit_group;");                               \
    } while (0)

    G_PREFETCH(0, 0);

    #pragma unroll 1
    for (int kt = 0; kt < 16; kt++) {
        int st = kt & 1;
        asm volatile("cp.async.wait_group 0;");
        __syncthreads();
        if (kt + 1 < 16) G_PREFETCH(kt + 1, st ^ 1);
        #pragma unroll
        for (int s8 = 0; s8 < 4; s8++) {
            int kb = s8 * 8 + L0;
            unsigned a[2][4];
            #pragma unroll
            for (int mt = 0; mt < 2; mt++) {
                int r = wm * 32 + mt * 16 + L2;
                a[mt][0] = As[st][r][kb];     a[mt][1] = As[st][r + 8][kb];
                a[mt][2] = As[st][r][kb + 4]; a[mt][3] = As[st][r + 8][kb + 4];
            }
            #pragma unroll
            for (int nt = 0; nt < 8; nt++) {
                int c = wn * 64 + nt * 8 + L2;
                unsigned b[2] = { Bs[st][c][kb], Bs[st][c][kb + 4] };
                mma16(acc[0][nt], a[0], b);
                mma16(acc[1][nt], a[1], b);
            }
        }
    }

    // ---- fused Poincare epilogue (scalars from L2-resident globals) ----
    int head = (n0 >> 6) + wn;
    #pragma unroll
    for (int mt = 0; mt < 2; mt++) {
        #pragma unroll
        for (int hh = 0; hh < 2; hh++) {
            int rloc = wm * 32 + mt * 16 + hh * 8 + L2;
            float cx2 = g_rowsq[m0 + rloc];
            float invden = frcp_a(fmaxf(1.0f - cx2, 1e-15f));
            float opc = 1.0f + cx2;
            float sq = 0.f;
            #pragma unroll
            for (int nt = 0; nt < 8; nt++) {
                int cl = wn * 64 + nt * 8 + 2 * L0;
                float4 cs0 = g_cols[which][n0 + cl];
                float4 cs1 = g_cols[which][n0 + cl + 1];
                #pragma unroll
                for (int u = 0; u < 2; u++) {
                    float4 cs = u ? cs1 : cs0;
                    float xz  = acc[mt][nt][hh * 2 + u];
                    float arg = fmaf(xz, cs.x, -opc * cs.z) * invden;
                    float aa  = fabsf(arg);
                    float A   = aa + fsqrt_a(fmaf(aa, aa, 1.0f));
                    float tE  = fex2_a(cs.y * flg2_a(A));
                    float y   = copysignf(0.5f * (tE - frcp_a(tE)), arg);
                    acc[mt][nt][hh * 2 + u] = y;
                    sq = fmaf(y, y, sq);
                }
            }
            sq += __shfl_xor_sync(0xffffffffu, sq, 1);
            sq += __shfl_xor_sync(0xffffffffu, sq, 2);
            float n1  = fmaxf(sqrtf(sq), 1e-15f);
            float s1  = (n1 > MAXN) ? (MAXN / n1) : 1.0f;
            float n1c = n1 * s1;
            float f   = 1.0f / (1.0f + sqrtf(1.0f + n1c * n1c));
            float n2  = fmaxf(n1c * f, 1e-15f);
            float s2v = (n2 > MAXN) ? (MAXN / n2) : 1.0f;
            float hs  = s1 * f * s2v;
            float n3  = n2 * s2v;
            int grow = m0 + rloc;
            if (L0 == 0) g_aux[which][grow * NH + head] = n3 * n3;
            #pragma unroll
            for (int nt = 0; nt < 8; nt++) {
                int cl = wn * 64 + nt * 8 + 2 * L0;
                *(float2*)&Cw[grow * DM + n0 + cl] =
                    make_float2(acc[mt][nt][hh * 2] * hs, acc[mt][nt][hh * 2 + 1] * hs);
            }
        }
    }
}

// ---------------------------------------------------------------------------
// Kernel 2: one-shot fp16 fragment prep for K / gamma*V.
// Warps 0-3: K steps 0-3; warps 4-7: V steps 0-3. 512 uints per (bh,kt,step).
// ---------------------------------------------------------------------------
__global__ __launch_bounds__(256)
void frag_prep_kernel(const float* __restrict__ mask) {
    __shared__ float Ks[64][68];
    __shared__ float Vs[64][68];

    int bh = blockIdx.x, kt = blockIdx.y;
    int b = bh >> 4, h = bh & 15;
    int kj0 = kt * 64;
    int t = threadIdx.x, lane = t & 31;
    int L2 = lane >> 2, L0 = lane & 3;
    int w = t >> 5;
    int s = w & 3;
    bool isV = (w >= 4);

    const float* K = g_qkv[1];
    const float* V = g_qkv[2];

    #pragma unroll
    for (int j = 0; j < 4; j++) {
        int idx = t + j * 256;
        int row = idx >> 4, c4 = (idx & 15) * 4;
        int gr = b * SS + kj0 + row;
        *(float4*)&Ks[row][c4] = *(const float4*)&K[gr * DM + h * DH + c4];
        float v2 = g_aux[2][gr * NH + h];
        float gam = 2.0f * frcp_a(fmaxf(1.0f - v2, 1e-15f));
        float4 vv = *(const float4*)&V[gr * DM + h * DH + c4];
        *(float4*)&Vs[row][c4] = make_float4(vv.x * gam, vv.y * gam, vv.z * gam, vv.w * gam);
    }
    if (t < 64) {
        int gr = b * SS + kj0 + t;
        float k2 = g_aux[1][gr * NH + h];
        float v2 = g_aux[2][gr * NH + h];
        g_sck[bh * 1024 + kj0 + t] =
            make_float4(k2, frcp_a(fmaxf(1.0f - k2, 1e-15f)),
                        2.0f * frcp_a(fmaxf(1.0f - v2, 1e-15f)) - 1.0f,
                        __expf(mask[b * SS + kj0 + t]));
    }
    __syncthreads();

    unsigned wf[16];
    if (!isV) {
        #pragma unroll
        for (int nt = 0; nt < 8; nt++) {
            int c = nt * 8 + L2;                 // key col
            wf[2*nt]   = packh2(Ks[c][s * 16 + 2 * L0],     Ks[c][s * 16 + 2 * L0 + 1]);
            wf[2*nt+1] = packh2(Ks[c][s * 16 + 2 * L0 + 8], Ks[c][s * 16 + 2 * L0 + 9]);
        }
    } else {
        #pragma unroll
        for (int nt = 0; nt < 8; nt++) {
            int d = nt * 8 + L2;                 // dh col
            wf[2*nt]   = packh2(Vs[s * 16 + 2 * L0][d],     Vs[s * 16 + 2 * L0 + 1][d]);
            wf[2*nt+1] = packh2(Vs[s * 16 + 2 * L0 + 8][d], Vs[s * 16 + 2 * L0 + 9][d]);
        }
    }
    unsigned base = (((unsigned)(bh * 16 + kt) * 4) + s) * 512 + lane * 4;
    unsigned* dst = isV ? g_vfrag : g_kfrag;
    #pragma unroll
    for (int i4 = 0; i4 < 4; i4++)
        *(uint4*)&dst[base + i4 * 128] = ((uint4*)wf)[i4];
}

// ---------------------------------------------------------------------------
// Kernel 3: flash-style hyperbolic attention, fp16 m16n8k16.
// ---------------------------------------------------------------------------
#define ATT_SMEM_WORDS (4096 + 128*34 + 8*64*4 + 128)
__global__ __launch_bounds__(256, 2)
void attn_kernel(float* __restrict__ out) {
    extern __shared__ unsigned smu[];
    unsigned* qf = smu;                                   // 4096: Q fp16 frags
    unsigned (*ps)[34] = (unsigned(*)[34])(smu + 4096);   // 128x34 P fp16x2
    float4* sws = (float4*)(smu + 4096 + 128*34);
    float* q2s  = (float*)(smu + 4096 + 128*34 + 8*64*4);

    int bh = blockIdx.x, qt = blockIdx.y;
    int b = bh >> 4, h = bh & 15;
    int t = threadIdx.x, wid = t >> 5, lane = t & 31;
    int L2 = lane >> 2, L0 = lane & 3;
    int qi0 = qt * 128;

    const float* Q = g_qkv[0];

    // ---- Q tile -> fp16 fragment-major smem ----
    #pragma unroll
    for (int j = 0; j < 8; j++) {
        int idx = t + j * 256;
        int row = idx >> 4, c4 = (idx & 15) * 4;
        float4 v = *(const float4*)&Q[(b * SS + qi0 + row) * DM + h * DH + c4];
        int rb = row >> 4, rr = row & 15;
        int s  = c4 >> 4;
        int j0 = (c4 & 15) >> 1;                       // even uint index in step
        int lane0 = (rr & 7) * 4 + (j0 & 3);
        int reg   = (rr >> 3) + 2 * (j0 >> 2);
        unsigned* qb = qf + (((rb * 4 + s) * 32 + lane0) * 4) + reg;
        qb[0] = packh2(v.x, v.y);
        qb[4] = packh2(v.z, v.w);                      // next lane, same reg
    }
    if (t < 128) q2s[t] = g_aux[0][(b * SS + qi0 + t) * NH + h];
    __syncthreads();

    int rA = wid * 16 + L2;
    float q2_0 = q2s[rA], q2_1 = q2s[rA + 8];
    float tiq0 = 2.0f * frcp_a(fmaxf(1.0f - q2_0, 1e-15f));
    float tiq1 = 2.0f * frcp_a(fmaxf(1.0f - q2_1, 1e-15f));

    float4* swsW = sws + wid * 64;
    const float4* sckB = g_sck + bh * 1024;

    float o[8][4] = {};
    float accd0 = 0.f, accd1 = 0.f;

    for (int kt = 0; kt < SS / 64; kt++) {
        int kj0 = kt * 64;
        size_t fb = (size_t)((unsigned)(bh * 16 + kt) * 4) * 512 + lane * 4;
        const unsigned* kfb = g_kfrag + fb;
        const unsigned* vfb = g_vfrag + fb;

        swsW[lane * 2]     = sckB[kj0 + lane * 2];
        swsW[lane * 2 + 1] = sckB[kj0 + lane * 2 + 1];
        __syncwarp();

        // ---- QK^T: 4 k16-steps ----
        float s[8][4] = {};
        #pragma unroll
        for (int st = 0; st < 4; st++) {
            uint4 af = *(uint4*)&qf[((wid * 4 + st) * 32 + lane) * 4];
            unsigned a[4] = { af.x, af.y, af.z, af.w };
            unsigned kw[16];
            #pragma unroll
            for (int i4 = 0; i4 < 4; i4++)
                *(uint4*)&kw[i4 * 4] = *(const uint4*)&kfb[st * 512 + i4 * 128];
            #pragma unroll
            for (int nt = 0; nt < 8; nt++) mma16(s[nt], a, &kw[nt * 2]);
        }

        // ---- score -> weight, accumulate denominator, stage P (fp16x2) ----
        #pragma unroll
        for (int nt = 0; nt < 8; nt++) {
            int j0 = nt * 8 + 2 * L0;
            float4 c0 = swsW[j0], c1 = swsW[j0 + 1];
            float w[4];
            #pragma unroll
            for (int e = 0; e < 4; e++) {
                float q2v = (e < 2) ? q2_0 : q2_1;
                float cc  = ((e < 2) ? tiq0 : tiq1) * ((e & 1) ? c1.y : c0.y);
                float k2v = (e & 1) ? c1.x : c0.x;
                float emv = (e & 1) ? c1.w : c0.w;
                float num = fmaxf(fmaf(-2.0f, s[nt][e], q2v + k2v), 1e-15f);
                float tt  = num * cc;
                float sr  = fsqrt_a(tt * (tt + 2.0f));
                w[e] = __fdividef(emv, (1.0f + tt) + sr);
            }
            accd0 = fmaf(w[0], c0.z, fmaf(w[1], c1.z, accd0));
            accd1 = fmaf(w[2], c0.z, fmaf(w[3], c1.z, accd1));
            ps[rA][nt * 4 + L0]     = packh2(w[0], w[1]);
            ps[rA + 8][nt * 4 + L0] = packh2(w[2], w[3]);
        }
        __syncwarp();

        // ---- P @ (gamma V): 4 k16-steps ----
        #pragma unroll
        for (int st = 0; st < 4; st++) {
            int kb = st * 8 + L0;
            unsigned a[4] = { ps[rA][kb], ps[rA + 8][kb], ps[rA][kb + 4], ps[rA + 8][kb + 4] };
            unsigned vw[16];
            #pragma unroll
            for (int i4 = 0; i4 < 4; i4++)
                *(uint4*)&vw[i4 * 4] = *(const uint4*)&vfb[st * 512 + i4 * 128];
            #pragma unroll
            for (int nt = 0; nt < 8; nt++) mma16(o[nt], a, &vw[nt * 2]);
        }
        __syncwarp();
    }

    // ---- finalize: gyromidpoint + project ----
    accd0 += __shfl_xor_sync(0xffffffffu, accd0, 1);
    accd0 += __shfl_xor_sync(0xffffffffu, accd0, 2);
    accd1 += __shfl_xor_sync(0xffffffffu, accd1, 1);
    accd1 += __shfl_xor_sync(0xffffffffu, accd1, 2);
    #pragma unroll
    for (int rh = 0; rh < 2; rh++) {
        float accd = rh ? accd1 : accd0;
        float invd = 1.0f / fmaxf(accd, 1e-10f);
        float tm[8][2];
        float sq = 0.f;
        #pragma unroll
        for (int nt = 0; nt < 8; nt++) {
            tm[nt][0] = o[nt][rh * 2 + 0] * invd;
            tm[nt][1] = o[nt][rh * 2 + 1] * invd;
            sq += tm[nt][0] * tm[nt][0] + tm[nt][1] * tm[nt][1];
        }
        sq += __shfl_xor_sync(0xffffffffu, sq, 1);
        sq += __shfl_xor_sync(0xffffffffu, sq, 2);
        float f = 1.0f / (1.0f + sqrtf(fmaxf(1.0f - sq, 1e-15f)));
        float n = fmaxf(sqrtf(sq) * f, 1e-15f);
        float s2 = (n > MAXN) ? (MAXN / n) : 1.0f;
        float g = f * s2;
        int qrow = qi0 + rA + rh * 8;
        #pragma unroll
        for (int nt = 0; nt < 8; nt++) {
            *(float2*)&out[(b * SS + qrow) * DM + h * DH + nt * 8 + 2 * L0] =
                make_float2(tm[nt][0] * g, tm[nt][1] * g);
        }
    }
}

// ---------------------------------------------------------------------------
extern "C" void kernel_launch(void* const* d_in, const int* in_sizes, int n_in,
                              void* d_out, int out_size) {
    const float* hidden = (const float*)d_in[0];
    const float* amask  = (const float*)d_in[1];
    const float* qz = (const float*)d_in[2];
    const float* qr = (const float*)d_in[3];
    const float* kz = (const float*)d_in[4];
    const float* kr = (const float*)d_in[5];
    const float* vz = (const float*)d_in[6];
    const float* vr = (const float*)d_in[7];
    float* out = (float*)d_out;

    static bool attr_done = false;
    if (!attr_done) {
        cudaFuncSetAttribute(attn_kernel, cudaFuncAttributeMaxDynamicSharedMemorySize,
                             ATT_SMEM_WORDS * 4);
        cudaFuncSetAttribute(gemm_proj_kernel, cudaFuncAttributeMaxDynamicSharedMemorySize,
                             GEMM_SMEM_WORDS * 4);
        attr_done = true;
    }

    xcvt_kernel<<<256, 256>>>(hidden);
    ztrans_kernel<<<dim3(16, 16, 3), 256>>>(qz, kz, vz);
    col_finish_kernel<<<12, 256>>>(qr, kr, vr);
    gemm_proj_kernel<<<dim3(MROWS / 128, DM / 128, 3), 256, GEMM_SMEM_WORDS * 4>>>();
    frag_prep_kernel<<<dim3(32, 16), 256>>>(amask);
    attn_kernel<<<dim3(BB * NH, SS / 128), 256, ATT_SMEM_WORDS * 4>>>(out);
}

// round 13
// speedup vs baseline: 2.0821x; 1.0537x over previous
#include <cuda_runtime.h>
#include <cuda_fp16.h>
#include <math.h>

#define BB 2
#define SS 1024
#define DM 1024
#define NH 16
#define DH 64
#define MROWS (BB*SS)
#define MAXN 0.996f

__device__ float g_qkv[3][MROWS*DM];
__device__ float g_aux[3][MROWS*NH];        // per-(row,head) final ||y||^2
__device__ unsigned g_kfrag[32*16*4*512];   // K  fp16 mma-frag order
__device__ unsigned g_vfrag[32*16*4*512];   // gamma*V fp16 mma-frag order
__device__ float4   g_sck[32*1024];         // per (bh,key): {k2, 1/(1-k2), gm1, e^mask}
__device__ unsigned g_xh[MROWS*DM/2];       // fp16x2(X)   [m][k/2]
__device__ unsigned g_zhT[3][DM*DM/2];      // fp16x2(Z^T) [n][k/2]
__device__ float    g_rowsq[MROWS];         // ||x_row||^2
__device__ float    g_colpart[3][16][DM];   // per-ktile col-norm partials
__device__ float4   g_cols[3][DM];          // {2cosh(2r)/zn, 2zn, sinh(2r), 0}

__device__ __forceinline__ unsigned packh2(float lo, float hi) {
    __half2 h = __floats2half2_rn(lo, hi);
    return *(unsigned*)&h;
}
__device__ __forceinline__ void mma16(float* d, const unsigned* a, const unsigned* b) {
    asm volatile("mma.sync.aligned.m16n8k16.row.col.f32.f16.f16.f32 "
        "{%0,%1,%2,%3}, {%4,%5,%6,%7}, {%8,%9}, {%0,%1,%2,%3};"
        : "+f"(d[0]), "+f"(d[1]), "+f"(d[2]), "+f"(d[3])
        : "r"(a[0]), "r"(a[1]), "r"(a[2]), "r"(a[3]), "r"(b[0]), "r"(b[1]));
}
__device__ __forceinline__ void ldsm4(unsigned* r, unsigned addr) {
    asm volatile("ldmatrix.sync.aligned.m8n8.x4.shared.b16 {%0,%1,%2,%3}, [%4];"
        : "=r"(r[0]), "=r"(r[1]), "=r"(r[2]), "=r"(r[3]) : "r"(addr));
}
__device__ __forceinline__ float fsqrt_a(float x){float r;asm("sqrt.approx.f32 %0,%1;":"=f"(r):"f"(x));return r;}
__device__ __forceinline__ float frcp_a (float x){float r;asm("rcp.approx.f32 %0,%1;" :"=f"(r):"f"(x));return r;}
__device__ __forceinline__ float flg2_a (float x){float r;asm("lg2.approx.f32 %0,%1;" :"=f"(r):"f"(x));return r;}
__device__ __forceinline__ float fex2_a (float x){float r;asm("ex2.approx.f32 %0,%1;" :"=f"(r):"f"(x));return r;}
__device__ __forceinline__ void cp16(unsigned s, const void* g) {
    asm volatile("cp.async.ca.shared.global [%0], [%1], 16;" :: "r"(s), "l"(g));
}

// ---------------------------------------------------------------------------
// Kernel 0a: X -> fp16 + row norms
// ---------------------------------------------------------------------------
__global__ __launch_bounds__(256)
void xcvt_kernel(const float* __restrict__ X) {
    int row = blockIdx.x * 8 + (threadIdx.x >> 5), lane = threadIdx.x & 31;
    const float* xr = X + row * DM;
    unsigned* xo = g_xh + row * (DM / 2);
    float s = 0.f;
    #pragma unroll
    for (int i = 0; i < 8; i++) {
        float4 v = *(const float4*)&xr[(i * 32 + lane) * 4];
        s = fmaf(v.x, v.x, fmaf(v.y, v.y, fmaf(v.z, v.z, fmaf(v.w, v.w, s))));
        *(uint2*)&xo[(i * 32 + lane) * 2] = make_uint2(packh2(v.x, v.y), packh2(v.z, v.w));
    }
    #pragma unroll
    for (int off = 16; off > 0; off >>= 1) s += __shfl_xor_sync(0xffffffffu, s, off);
    if (lane == 0) g_rowsq[row] = s;
}

// ---------------------------------------------------------------------------
// Kernel 0b: Z -> fp16 TRANSPOSED ([n][k]) via 64x64 smem tiles + col partials
// ---------------------------------------------------------------------------
__global__ __launch_bounds__(256)
void ztrans_kernel(const float* __restrict__ qz, const float* __restrict__ kz,
                   const float* __restrict__ vz) {
    __shared__ float tile[64][65];
    __shared__ float redc[16][64];
    int which = blockIdx.z;
    int k0 = blockIdx.x * 64, n0 = blockIdx.y * 64;
    const float* Z = (which == 0) ? qz : (which == 1) ? kz : vz;
    int t = threadIdx.x;
    float cp0 = 0.f, cp1 = 0.f, cp2 = 0.f, cp3 = 0.f;
    #pragma unroll
    for (int j = 0; j < 4; j++) {
        int idx = t + j * 256;
        int r = idx >> 4, c4 = (idx & 15) * 4;
        float4 v = *(const float4*)&Z[(k0 + r) * DM + n0 + c4];
        tile[r][c4] = v.x; tile[r][c4 + 1] = v.y;
        tile[r][c4 + 2] = v.z; tile[r][c4 + 3] = v.w;
        cp0 = fmaf(v.x, v.x, cp0); cp1 = fmaf(v.y, v.y, cp1);
        cp2 = fmaf(v.z, v.z, cp2); cp3 = fmaf(v.w, v.w, cp3);
    }
    int cg = (t & 15) * 4;
    redc[t >> 4][cg] = cp0; redc[t >> 4][cg + 1] = cp1;
    redc[t >> 4][cg + 2] = cp2; redc[t >> 4][cg + 3] = cp3;
    __syncthreads();
    if (t < 64) {
        float s = 0.f;
        #pragma unroll
        for (int g = 0; g < 16; g++) s += redc[g][t];
        g_colpart[which][blockIdx.x][n0 + t] = s;
    }
    #pragma unroll
    for (int j = 0; j < 4; j++) {
        int idx = t + j * 256;
        int nr = idx >> 4, kc4 = (idx & 15) * 4;
        *(uint2*)&g_zhT[which][(n0 + nr) * (DM / 2) + (k0 + kc4) / 2] =
            make_uint2(packh2(tile[kc4][nr], tile[kc4 + 1][nr]),
                       packh2(tile[kc4 + 2][nr], tile[kc4 + 3][nr]));
    }
}

// ---------------------------------------------------------------------------
// Kernel 0c: finish column scalars (sum 16 partials)
// ---------------------------------------------------------------------------
__global__ __launch_bounds__(256)
void col_finish_kernel(const float* __restrict__ qr, const float* __restrict__ kr,
                       const float* __restrict__ vr) {
    int gid = blockIdx.x * 256 + threadIdx.x;   // 0..3071
    int which = gid >> 10, col = gid & 1023;
    const float* R = (which == 0) ? qr : (which == 1) ? kr : vr;
    float zs = 0.f;
    #pragma unroll
    for (int p = 0; p < 16; p++) zs += g_colpart[which][p][col];
    float zn = fmaxf(fsqrt_a(zs), 1e-15f);
    float rv = 2.0f * R[col];
    float e  = fex2_a(rv * 1.44269504f);
    float ie = frcp_a(e);
    g_cols[which][col] = make_float4((e + ie) * frcp_a(zn), 2.0f * zn, 0.5f * (e - ie), 0.f);
}

// ---------------------------------------------------------------------------
// Kernel 1: fp16 m16n8k16 GEMM, cp.async 2-stage pipeline, ldmatrix fragment
// loads (6 LDSM per k16-step vs 24 LDS.32), fused Poincare epilogue.
// ---------------------------------------------------------------------------
#define GEMM_STAGE (128*36)                    // uints per stage per operand
#define GEMM_SMEM_WORDS (4*GEMM_STAGE)
__global__ __launch_bounds__(256, 2)
void gemm_proj_kernel() {
    int which = blockIdx.z;
    const unsigned* Xh = g_xh;
    const unsigned* Zh = g_zhT[which];
    float* Cw = g_qkv[which];

    extern __shared__ unsigned gsm[];
    unsigned sbase = (unsigned)__cvta_generic_to_shared(gsm);
    unsigned sa = sbase, sb = sbase + 2 * GEMM_STAGE * 4;

    int t = threadIdx.x;
    int wid = t >> 5, lane = t & 31;
    int L2 = lane >> 2, L0 = lane & 3;
    int wm = wid >> 1, wn = wid & 1;
    int m0 = blockIdx.x * 128, n0 = blockIdx.y * 128;

    // ldmatrix per-lane address components (mat = lane>>3, r = lane&7)
    int mat = lane >> 3, lr = lane & 7;
    int a_row = (mat & 1) * 8 + lr;      // A: mats (m0-7,klo),(m8-15,klo),(m0-7,khi),(m8-15,khi)
    int a_kof = (mat >> 1) * 4;
    int b_row = (mat >> 1) * 8 + lr;     // B: mats (n0-7,klo),(n0-7,khi),(n8-15,klo),(n8-15,khi)
    int b_kof = (mat & 1) * 4;

    float acc[2][8][4] = {};

    // per-tile copy: 128 rows x 8 segs (16B) for each operand; 4+4 per thread
#define G_PREFETCH(kc, sg) do {                                               \
        _Pragma("unroll")                                                     \
        for (int j_ = 0; j_ < 4; j_++) {                                      \
            int u_ = t + j_ * 256;                                            \
            int row_ = u_ >> 3, seg_ = u_ & 7;                                \
            unsigned off_ = (((unsigned)(sg) * 128 + row_) * 36 + seg_ * 4) * 4; \
            cp16(sa + off_, &Xh[(m0 + row_) * (DM/2) + (kc) * 32 + seg_ * 4]); \
            cp16(sb + off_, &Zh[(n0 + row_) * (DM/2) + (kc) * 32 + seg_ * 4]); \
        }                                                                     \
        asm volatile("cp.async.commit_group;");                               \
    } while (0)

    G_PREFETCH(0, 0);

    #pragma unroll 1
    for (int kt = 0; kt < 16; kt++) {
        int st = kt & 1;
        asm volatile("cp.async.wait_group 0;");
        __syncthreads();
        if (kt + 1 < 16) G_PREFETCH(kt + 1, st ^ 1);
        unsigned abase = sa + ((unsigned)(st * 128 + wm * 32 + a_row) * 36 + a_kof) * 4;
        unsigned bbase = sb + ((unsigned)(st * 128 + wn * 64 + b_row) * 36 + b_kof) * 4;
        #pragma unroll
        for (int s8 = 0; s8 < 4; s8++) {
            unsigned a[2][4], b[4][4];
            ldsm4(a[0], abase + (s8 * 8) * 4);
            ldsm4(a[1], abase + (16 * 36 + s8 * 8) * 4);
            #pragma unroll
            for (int p = 0; p < 4; p++)
                ldsm4(b[p], bbase + ((p * 16) * 36 + s8 * 8) * 4);
            #pragma unroll
            for (int p = 0; p < 4; p++) {
                mma16(acc[0][p * 2],     a[0], &b[p][0]);
                mma16(acc[0][p * 2 + 1], a[0], &b[p][2]);
                mma16(acc[1][p * 2],     a[1], &b[p][0]);
                mma16(acc[1][p * 2 + 1], a[1], &b[p][2]);
            }
        }
    }

    // ---- fused Poincare epilogue (scalars from L2-resident globals) ----
    int head = (n0 >> 6) + wn;
    #pragma unroll
    for (int mt = 0; mt < 2; mt++) {
        #pragma unroll
        for (int hh = 0; hh < 2; hh++) {
            int rloc = wm * 32 + mt * 16 + hh * 8 + L2;
            float cx2 = g_rowsq[m0 + rloc];
            float invden = frcp_a(fmaxf(1.0f - cx2, 1e-15f));
            float opc = 1.0f + cx2;
            float sq = 0.f;
            #pragma unroll
            for (int nt = 0; nt < 8; nt++) {
                int cl = wn * 64 + nt * 8 + 2 * L0;
                float4 cs0 = g_cols[which][n0 + cl];
                float4 cs1 = g_cols[which][n0 + cl + 1];
                #pragma unroll
                for (int u = 0; u < 2; u++) {
                    float4 cs = u ? cs1 : cs0;
                    float xz  = acc[mt][nt][hh * 2 + u];
                    float arg = fmaf(xz, cs.x, -opc * cs.z) * invden;
                    float aa  = fabsf(arg);
                    float A   = aa + fsqrt_a(fmaf(aa, aa, 1.0f));
                    float tE  = fex2_a(cs.y * flg2_a(A));
                    float y   = copysignf(0.5f * (tE - frcp_a(tE)), arg);
                    acc[mt][nt][hh * 2 + u] = y;
                    sq = fmaf(y, y, sq);
                }
            }
            sq += __shfl_xor_sync(0xffffffffu, sq, 1);
            sq += __shfl_xor_sync(0xffffffffu, sq, 2);
            float n1  = fmaxf(sqrtf(sq), 1e-15f);
            float s1  = (n1 > MAXN) ? (MAXN / n1) : 1.0f;
            float n1c = n1 * s1;
            float f   = 1.0f / (1.0f + sqrtf(1.0f + n1c * n1c));
            float n2  = fmaxf(n1c * f, 1e-15f);
            float s2v = (n2 > MAXN) ? (MAXN / n2) : 1.0f;
            float hs  = s1 * f * s2v;
            float n3  = n2 * s2v;
            int grow = m0 + rloc;
            if (L0 == 0) g_aux[which][grow * NH + head] = n3 * n3;
            #pragma unroll
            for (int nt = 0; nt < 8; nt++) {
                int cl = wn * 64 + nt * 8 + 2 * L0;
                *(float2*)&Cw[grow * DM + n0 + cl] =
                    make_float2(acc[mt][nt][hh * 2] * hs, acc[mt][nt][hh * 2 + 1] * hs);
            }
        }
    }
}

// ---------------------------------------------------------------------------
// Kernel 2: one-shot fp16 fragment prep for K / gamma*V.
// ---------------------------------------------------------------------------
__global__ __launch_bounds__(256)
void frag_prep_kernel(const float* __restrict__ mask) {
    __shared__ float Ks[64][68];
    __shared__ float Vs[64][68];

    int bh = blockIdx.x, kt = blockIdx.y;
    int b = bh >> 4, h = bh & 15;
    int kj0 = kt * 64;
    int t = threadIdx.x, lane = t & 31;
    int L2 = lane >> 2, L0 = lane & 3;
    int w = t >> 5;
    int s = w & 3;
    bool isV = (w >= 4);

    const float* K = g_qkv[1];
    const float* V = g_qkv[2];

    #pragma unroll
    for (int j = 0; j < 4; j++) {
        int idx = t + j * 256;
        int row = idx >> 4, c4 = (idx & 15) * 4;
        int gr = b * SS + kj0 + row;
        *(float4*)&Ks[row][c4] = *(const float4*)&K[gr * DM + h * DH + c4];
        float v2 = g_aux[2][gr * NH + h];
        float gam = 2.0f * frcp_a(fmaxf(1.0f - v2, 1e-15f));
        float4 vv = *(const float4*)&V[gr * DM + h * DH + c4];
        *(float4*)&Vs[row][c4] = make_float4(vv.x * gam, vv.y * gam, vv.z * gam, vv.w * gam);
    }
    if (t < 64) {
        int gr = b * SS + kj0 + t;
        float k2 = g_aux[1][gr * NH + h];
        float v2 = g_aux[2][gr * NH + h];
        g_sck[bh * 1024 + kj0 + t] =
            make_float4(k2, frcp_a(fmaxf(1.0f - k2, 1e-15f)),
                        2.0f * frcp_a(fmaxf(1.0f - v2, 1e-15f)) - 1.0f,
                        __expf(mask[b * SS + kj0 + t]));
    }
    __syncthreads();

    unsigned wf[16];
    if (!isV) {
        #pragma unroll
        for (int nt = 0; nt < 8; nt++) {
            int c = nt * 8 + L2;
            wf[2*nt]   = packh2(Ks[c][s * 16 + 2 * L0],     Ks[c][s * 16 + 2 * L0 + 1]);
            wf[2*nt+1] = packh2(Ks[c][s * 16 + 2 * L0 + 8], Ks[c][s * 16 + 2 * L0 + 9]);
        }
    } else {
        #pragma unroll
        for (int nt = 0; nt < 8; nt++) {
            int d = nt * 8 + L2;
            wf[2*nt]   = packh2(Vs[s * 16 + 2 * L0][d],     Vs[s * 16 + 2 * L0 + 1][d]);
            wf[2*nt+1] = packh2(Vs[s * 16 + 2 * L0 + 8][d], Vs[s * 16 + 2 * L0 + 9][d]);
        }
    }
    unsigned base = (((unsigned)(bh * 16 + kt) * 4) + s) * 512 + lane * 4;
    unsigned* dst = isV ? g_vfrag : g_kfrag;
    #pragma unroll
    for (int i4 = 0; i4 < 4; i4++)
        *(uint4*)&dst[base + i4 * 128] = ((uint4*)wf)[i4];
}

// ---------------------------------------------------------------------------
// Kernel 3: flash-style hyperbolic attention, fp16 m16n8k16 (unchanged)
// ---------------------------------------------------------------------------
#define ATT_SMEM_WORDS (4096 + 128*34 + 8*64*4 + 128)
__global__ __launch_bounds__(256, 2)
void attn_kernel(float* __restrict__ out) {
    extern __shared__ unsigned smu[];
    unsigned* qf = smu;                                   // 4096: Q fp16 frags
    unsigned (*ps)[34] = (unsigned(*)[34])(smu + 4096);   // 128x34 P fp16x2
    float4* sws = (float4*)(smu + 4096 + 128*34);
    float* q2s  = (float*)(smu + 4096 + 128*34 + 8*64*4);

    int bh = blockIdx.x, qt = blockIdx.y;
    int b = bh >> 4, h = bh & 15;
    int t = threadIdx.x, wid = t >> 5, lane = t & 31;
    int L2 = lane >> 2, L0 = lane & 3;
    int qi0 = qt * 128;

    const float* Q = g_qkv[0];

    #pragma unroll
    for (int j = 0; j < 8; j++) {
        int idx = t + j * 256;
        int row = idx >> 4, c4 = (idx & 15) * 4;
        float4 v = *(const float4*)&Q[(b * SS + qi0 + row) * DM + h * DH + c4];
        int rb = row >> 4, rr = row & 15;
        int s  = c4 >> 4;
        int j0 = (c4 & 15) >> 1;
        int lane0 = (rr & 7) * 4 + (j0 & 3);
        int reg   = (rr >> 3) + 2 * (j0 >> 2);
        unsigned* qb = qf + (((rb * 4 + s) * 32 + lane0) * 4) + reg;
        qb[0] = packh2(v.x, v.y);
        qb[4] = packh2(v.z, v.w);
    }
    if (t < 128) q2s[t] = g_aux[0][(b * SS + qi0 + t) * NH + h];
    __syncthreads();

    int rA = wid * 16 + L2;
    float q2_0 = q2s[rA], q2_1 = q2s[rA + 8];
    float tiq0 = 2.0f * frcp_a(fmaxf(1.0f - q2_0, 1e-15f));
    float tiq1 = 2.0f * frcp_a(fmaxf(1.0f - q2_1, 1e-15f));

    float4* swsW = sws + wid * 64;
    const float4* sckB = g_sck + bh * 1024;

    float o[8][4] = {};
    float accd0 = 0.f, accd1 = 0.f;

    for (int kt = 0; kt < SS / 64; kt++) {
        int kj0 = kt * 64;
        size_t fb = (size_t)((unsigned)(bh * 16 + kt) * 4) * 512 + lane * 4;
        const unsigned* kfb = g_kfrag + fb;
        const unsigned* vfb = g_vfrag + fb;

        swsW[lane * 2]     = sckB[kj0 + lane * 2];
        swsW[lane * 2 + 1] = sckB[kj0 + lane * 2 + 1];
        __syncwarp();

        float s[8][4] = {};
        #pragma unroll
        for (int st = 0; st < 4; st++) {
            uint4 af = *(uint4*)&qf[((wid * 4 + st) * 32 + lane) * 4];
            unsigned a[4] = { af.x, af.y, af.z, af.w };
            unsigned kw[16];
            #pragma unroll
            for (int i4 = 0; i4 < 4; i4++)
                *(uint4*)&kw[i4 * 4] = *(const uint4*)&kfb[st * 512 + i4 * 128];
            #pragma unroll
            for (int nt = 0; nt < 8; nt++) mma16(s[nt], a, &kw[nt * 2]);
        }

        #pragma unroll
        for (int nt = 0; nt < 8; nt++) {
            int j0 = nt * 8 + 2 * L0;
            float4 c0 = swsW[j0], c1 = swsW[j0 + 1];
            float w[4];
            #pragma unroll
            for (int e = 0; e < 4; e++) {
                float q2v = (e < 2) ? q2_0 : q2_1;
                float cc  = ((e < 2) ? tiq0 : tiq1) * ((e & 1) ? c1.y : c0.y);
                float k2v = (e & 1) ? c1.x : c0.x;
                float emv = (e & 1) ? c1.w : c0.w;
                float num = fmaxf(fmaf(-2.0f, s[nt][e], q2v + k2v), 1e-15f);
                float tt  = num * cc;
                float sr  = fsqrt_a(tt * (tt + 2.0f));
                w[e] = __fdividef(emv, (1.0f + tt) + sr);
            }
            accd0 = fmaf(w[0], c0.z, fmaf(w[1], c1.z, accd0));
            accd1 = fmaf(w[2], c0.z, fmaf(w[3], c1.z, accd1));
            ps[rA][nt * 4 + L0]     = packh2(w[0], w[1]);
            ps[rA + 8][nt * 4 + L0] = packh2(w[2], w[3]);
        }
        __syncwarp();

        #pragma unroll
        for (int st = 0; st < 4; st++) {
            int kb = st * 8 + L0;
            unsigned a[4] = { ps[rA][kb], ps[rA + 8][kb], ps[rA][kb + 4], ps[rA + 8][kb + 4] };
            unsigned vw[16];
            #pragma unroll
            for (int i4 = 0; i4 < 4; i4++)
                *(uint4*)&vw[i4 * 4] = *(const uint4*)&vfb[st * 512 + i4 * 128];
            #pragma unroll
            for (int nt = 0; nt < 8; nt++) mma16(o[nt], a, &vw[nt * 2]);
        }
        __syncwarp();
    }

    accd0 += __shfl_xor_sync(0xffffffffu, accd0, 1);
    accd0 += __shfl_xor_sync(0xffffffffu, accd0, 2);
    accd1 += __shfl_xor_sync(0xffffffffu, accd1, 1);
    accd1 += __shfl_xor_sync(0xffffffffu, accd1, 2);
    #pragma unroll
    for (int rh = 0; rh < 2; rh++) {
        float accd = rh ? accd1 : accd0;
        float invd = 1.0f / fmaxf(accd, 1e-10f);
        float tm[8][2];
        float sq = 0.f;
        #pragma unroll
        for (int nt = 0; nt < 8; nt++) {
            tm[nt][0] = o[nt][rh * 2 + 0] * invd;
            tm[nt][1] = o[nt][rh * 2 + 1] * invd;
            sq += tm[nt][0] * tm[nt][0] + tm[nt][1] * tm[nt][1];
        }
        sq += __shfl_xor_sync(0xffffffffu, sq, 1);
        sq += __shfl_xor_sync(0xffffffffu, sq, 2);
        float f = 1.0f / (1.0f + sqrtf(fmaxf(1.0f - sq, 1e-15f)));
        float n = fmaxf(sqrtf(sq) * f, 1e-15f);
        float s2 = (n > MAXN) ? (MAXN / n) : 1.0f;
        float g = f * s2;
        int qrow = qi0 + rA + rh * 8;
        #pragma unroll
        for (int nt = 0; nt < 8; nt++) {
            *(float2*)&out[(b * SS + qrow) * DM + h * DH + nt * 8 + 2 * L0] =
                make_float2(tm[nt][0] * g, tm[nt][1] * g);
        }
    }
}

// ---------------------------------------------------------------------------
extern "C" void kernel_launch(void* const* d_in, const int* in_sizes, int n_in,
                              void* d_out, int out_size) {
    const float* hidden = (const float*)d_in[0];
    const float* amask  = (const float*)d_in[1];
    const float* qz = (const float*)d_in[2];
    const float* qr = (const float*)d_in[3];
    const float* kz = (const float*)d_in[4];
    const float* kr = (const float*)d_in[5];
    const float* vz = (const float*)d_in[6];
    const float* vr = (const float*)d_in[7];
    float* out = (float*)d_out;

    static bool attr_done = false;
    if (!attr_done) {
        cudaFuncSetAttribute(attn_kernel, cudaFuncAttributeMaxDynamicSharedMemorySize,
                             ATT_SMEM_WORDS * 4);
        cudaFuncSetAttribute(gemm_proj_kernel, cudaFuncAttributeMaxDynamicSharedMemorySize,
                             GEMM_SMEM_WORDS * 4);
        attr_done = true;
    }

    xcvt_kernel<<<256, 256>>>(hidden);
    ztrans_kernel<<<dim3(16, 16, 3), 256>>>(qz, kz, vz);
    col_finish_kernel<<<12, 256>>>(qr, kr, vr);
    gemm_proj_kernel<<<dim3(MROWS / 128, DM / 128, 3), 256, GEMM_SMEM_WORDS * 4>>>();
    frag_prep_kernel<<<dim3(32, 16), 256>>>(amask);
    attn_kernel<<<dim3(BB * NH, SS / 128), 256, ATT_SMEM_WORDS * 4>>>(out);
}